// round 2
// baseline (speedup 1.0000x reference)
#include <cuda_runtime.h>
#include <math.h>

// ---------------- device scratch ----------------
__device__ float  g_xt [6291456];     // x NHWC [32,256,256,3]
__device__ float  g_h1 [33554432];    // [32,128,128,64] NHWC
__device__ float  g_h2 [16777216];    // [32,64,64,128]  NHWC
__device__ float  g_z  [8388608];     // [32,64,64,64]   NHWC == flat [131072,64]
__device__ float  g_q  [8388608];
__device__ float  g_d1 [67108864];    // [32,128,128,128] NHWC
__device__ float  g_d2 [134217728];   // [32,256,256,64]  NHWC
__device__ float  g_col[268435456];   // im2col / scores scratch (1 GiB)
__device__ float  g_wb1[64*48];
__device__ float  g_wb2[128*1024];
__device__ float  g_wb3[64*1152];
__device__ float  g_wbd[32768];
__device__ float  g_enorm[512];
__device__ double g_loss;

// ---------------- small kernels ----------------
__global__ void nchw_to_nhwc_x(const float* __restrict__ in, float* __restrict__ out) {
    int idx = blockIdx.x * 256 + threadIdx.x;            // 32*65536
    int n = idx >> 16, yx = idx & 65535;
    const float* ib = in + (long)n * 196608 + yx;
    float* ob = out + (long)idx * 3;
    ob[0] = ib[0]; ob[1] = ib[65536]; ob[2] = ib[131072];
}

// w[co][ci][ky][kx] -> bw[co][(ky*KW+kx)*Cin+ci]
__global__ void pack_conv_w(const float* __restrict__ w, float* __restrict__ bw,
                            int Cout, int Cin, int KH, int KW) {
    int idx = blockIdx.x * 256 + threadIdx.x;
    int K = Cin * KH * KW;
    if (idx >= Cout * K) return;
    int co = idx / K, rem = idx % K;
    int ci = rem / (KH * KW), r2 = rem % (KH * KW);
    bw[(long)co * K + r2 * Cin + ci] = w[idx];
}

// deconv k4s2p1 parity pack: w[ci][co][4][4] -> bw[co][(ty*2+tx)*Cin+ci], ky=(1-py)+2ty
__global__ void pack_deconv_w(const float* __restrict__ w, float* __restrict__ bw,
                              int Cin, int Cout, int py, int px) {
    int idx = blockIdx.x * 256 + threadIdx.x;
    if (idx >= Cout * Cin * 4) return;
    int co = idx / (Cin * 4), rem = idx % (Cin * 4);
    int ci = rem / 4, tt = rem % 4;
    int ky = (1 - py) + 2 * (tt >> 1), kx = (1 - px) + 2 * (tt & 1);
    bw[(long)co * (4 * Cin) + tt * Cin + ci] = w[(((long)ci * Cout + co) * 4 + ky) * 4 + kx];
}

__global__ void compute_enorm(const float* __restrict__ emb, float* __restrict__ en) {
    int j = blockIdx.x * 256 + threadIdx.x;
    if (j >= 512) return;
    float s = 0.f;
    const float* e = emb + (long)j * 64;
#pragma unroll 8
    for (int d = 0; d < 64; ++d) { float v = e[d]; s = fmaf(v, v, s); }
    en[j] = s;
}

__global__ void zero_loss() { g_loss = 0.0; }
__global__ void finalize_loss(float* out, long pos) {
    out[pos] = (float)(1.25 * g_loss / 8388608.0);
}

// ---------------- im2col ----------------
template<int CIN, int KH, int KW, int ST, int PAD, int IH, int IW, int OW, int KT, int MB>
__global__ void __launch_bounds__(256)
im2col_conv(const float* __restrict__ in, float* __restrict__ col) {
    constexpr int K = KH * KW * CIN;
    int mi = threadIdx.x / KT, kt = threadIdx.x % KT;
    int m = blockIdx.x * MB + mi;
    int n = m / ((IH/ST)*(IW/ST) * 0 + (OW * OW)); // OW==OH here
    int r = m % (OW * OW);
    int oy = r / OW, ox = r % OW;
    const float* inb = in + (long)n * IH * IW * CIN;
    float* colr = col + (long)m * K;
    for (int k = kt; k < K; k += KT) {
        int ci = k % CIN, t = k / CIN;
        int kx = t % KW, ky = t / KW;
        int iy = oy * ST - PAD + ky, ix = ox * ST - PAD + kx;
        float v = 0.f;
        if (iy >= 0 && iy < IH && ix >= 0 && ix < IW)
            v = inb[((long)iy * IW + ix) * CIN + ci];
        colr[k] = v;
    }
}

template<int CIN, int IH, int IW, int KT, int MB>
__global__ void __launch_bounds__(256)
im2col_deconv(const float* __restrict__ in, float* __restrict__ col, int py, int px) {
    constexpr int K = 4 * CIN;
    int mi = threadIdx.x / KT, kt = threadIdx.x % KT;
    int m = blockIdx.x * MB + mi;
    int n = m / (IH * IW), r = m % (IH * IW);
    int u = r / IW, v = r % IW;
    const float* inb = in + (long)n * IH * IW * CIN;
    float* colr = col + (long)m * K;
    for (int k = kt; k < K; k += KT) {
        int ci = k % CIN, t = k / CIN;
        int iy = u + py - (t >> 1), ix = v + px - (t & 1);
        float val = 0.f;
        if (iy >= 0 && iy < IH && ix >= 0 && ix < IW)
            val = inb[((long)iy * IW + ix) * CIN + ci];
        colr[k] = val;
    }
}

// ---------------- SGEMM: C = A[M,K] * B[N,K]^T ----------------
struct Epi {
    float* out; const float* bias;
    int mode, act, ldc;          // mode 0: row-major; 1: deconv NHWC scatter
    int MPN, OV, W2, C, py, px;
    long nstride;
};

__global__ void __launch_bounds__(256)
sgemm(const float* __restrict__ A, const float* __restrict__ Bm, int K, Epi ep) {
    __shared__ float As[16][132];
    __shared__ float Bs[16][68];
    const int tid = threadIdx.x;
    const int m0 = blockIdx.y * 128, n0 = blockIdx.x * 64;
    const int tx = tid & 15, ty = tid >> 4;
    const int ra = tid >> 1, ca = (tid & 1) * 8;
    const int rb = tid >> 2, cb = (tid & 3) * 4;
    float acc[8][4] = {};
    const float* Aptr = A  + (long)(m0 + ra) * K + ca;
    const float* Bptr = Bm + (long)(n0 + rb) * K + cb;

    for (int k0 = 0; k0 < K; k0 += 16) {
        float4 a0 = *(const float4*)(Aptr + k0);
        float4 a1 = *(const float4*)(Aptr + k0 + 4);
        float4 b0 = *(const float4*)(Bptr + k0);
        As[ca+0][ra]=a0.x; As[ca+1][ra]=a0.y; As[ca+2][ra]=a0.z; As[ca+3][ra]=a0.w;
        As[ca+4][ra]=a1.x; As[ca+5][ra]=a1.y; As[ca+6][ra]=a1.z; As[ca+7][ra]=a1.w;
        Bs[cb+0][rb]=b0.x; Bs[cb+1][rb]=b0.y; Bs[cb+2][rb]=b0.z; Bs[cb+3][rb]=b0.w;
        __syncthreads();
#pragma unroll
        for (int kk = 0; kk < 16; ++kk) {
            float4 aA = *(const float4*)&As[kk][ty*8];
            float4 aB = *(const float4*)&As[kk][ty*8+4];
            float4 bb = *(const float4*)&Bs[kk][tx*4];
            float av[8] = {aA.x,aA.y,aA.z,aA.w,aB.x,aB.y,aB.z,aB.w};
            float bv[4] = {bb.x,bb.y,bb.z,bb.w};
#pragma unroll
            for (int i = 0; i < 8; ++i)
#pragma unroll
                for (int j = 0; j < 4; ++j)
                    acc[i][j] = fmaf(av[i], bv[j], acc[i][j]);
        }
        __syncthreads();
    }

    const int n_base = n0 + tx * 4;
    float bvals[4];
#pragma unroll
    for (int j = 0; j < 4; ++j) bvals[j] = ep.bias ? ep.bias[n_base + j] : 0.f;
#pragma unroll
    for (int i = 0; i < 8; ++i) {
        int m = m0 + ty * 8 + i;
        long base;
        if (ep.mode == 0) base = (long)m * ep.ldc + n_base;
        else {
            int nn = m / ep.MPN, r = m % ep.MPN;
            int u = r / ep.OV, v = r % ep.OV;
            base = (long)nn * ep.nstride +
                   ((long)(2*u + ep.py) * ep.W2 + (2*v + ep.px)) * ep.C + n_base;
        }
#pragma unroll
        for (int j = 0; j < 4; ++j) {
            float vv = acc[i][j] + bvals[j];
            if (ep.act) vv = fmaxf(vv, 0.f);
            ep.out[base + j] = vv;
        }
    }
}

// ---------------- VQ: argmin + gather + loss ----------------
__global__ void __launch_bounds__(256)
vq_kernel(const float* __restrict__ scores, const float* __restrict__ z,
          const float* __restrict__ emb, const float* __restrict__ enorm,
          float* __restrict__ q) {
    __shared__ float wsq[8];
    const int lane = threadIdx.x & 31, wid = threadIdx.x >> 5;
    const long m = (long)blockIdx.x * 8 + wid;
    const float* srow = scores + m * 512;
    float best = 3.4e38f; int bidx = 0x7fffffff;
    for (int j = lane; j < 512; j += 32) {
        float d = enorm[j] - 2.f * srow[j];
        if (d < best) { best = d; bidx = j; }
    }
#pragma unroll
    for (int o = 16; o; o >>= 1) {
        float ob = __shfl_xor_sync(0xffffffffu, best, o);
        int   oi = __shfl_xor_sync(0xffffffffu, bidx, o);
        if (ob < best || (ob == best && oi < bidx)) { best = ob; bidx = oi; }
    }
    float2 e  = ((const float2*)emb)[(long)bidx * 32 + lane];
    float2 zz = ((const float2*)z)[m * 32 + lane];
    ((float2*)q)[m * 32 + lane] = e;
    float d0 = e.x - zz.x, d1 = e.y - zz.y;
    float sq = fmaf(d0, d0, d1 * d1);
#pragma unroll
    for (int o = 16; o; o >>= 1) sq += __shfl_xor_sync(0xffffffffu, sq, o);
    if (lane == 0) wsq[wid] = sq;
    __syncthreads();
    if (threadIdx.x == 0) {
        float s = 0.f;
#pragma unroll
        for (int i = 0; i < 8; ++i) s += wsq[i];
        atomicAdd(&g_loss, (double)s);
    }
}

// ---------------- final deconv 64->3 k3 s1 p1 + sigmoid (direct, NCHW out) ----------------
__global__ void __launch_bounds__(256)
deconv3_sigmoid(const float* __restrict__ in, const float* __restrict__ w,
                const float* __restrict__ bias, float* __restrict__ out) {
    __shared__ float sIn[8][18][66];
    __shared__ float sW[1728];
    const int t = threadIdx.x, n = blockIdx.z;
    const int y0 = blockIdx.y * 16, x0 = blockIdx.x * 64;
    for (int i = t; i < 1728; i += 256) sW[i] = w[i];
    const int ty = t >> 4, txq = t & 15;
    float acc[3][4] = {};
    for (int cc = 0; cc < 8; ++cc) {
        __syncthreads();
        for (int idx = t; idx < 8*18*66; idx += 256) {
            int ci = idx & 7, rr = idx >> 3;
            int sx = rr % 66, sy = rr / 66;
            int gy = y0 - 1 + sy, gx = x0 - 1 + sx;
            float v = 0.f;
            if (gy >= 0 && gy < 256 && gx >= 0 && gx < 256)
                v = in[(((long)n * 256 + gy) * 256 + gx) * 64 + cc * 8 + ci];
            sIn[ci][sy][sx] = v;
        }
        __syncthreads();
#pragma unroll
        for (int c8 = 0; c8 < 8; ++c8) {
            const int ci = cc * 8 + c8;
#pragma unroll
            for (int ky = 0; ky < 3; ++ky)
#pragma unroll
            for (int kx = 0; kx < 3; ++kx) {
                const float* wp = &sW[ci*27 + ky*3 + kx];
                float w0 = wp[0], w1 = wp[9], w2 = wp[18];
                const float* ip = &sIn[c8][ty + 2 - ky][txq*4 + 2 - kx];
#pragma unroll
                for (int qq = 0; qq < 4; ++qq) {
                    float iv = ip[qq];
                    acc[0][qq] = fmaf(iv, w0, acc[0][qq]);
                    acc[1][qq] = fmaf(iv, w1, acc[1][qq]);
                    acc[2][qq] = fmaf(iv, w2, acc[2][qq]);
                }
            }
        }
    }
#pragma unroll
    for (int co = 0; co < 3; ++co) {
        float bb = bias[co];
#pragma unroll
        for (int qq = 0; qq < 4; ++qq) {
            float v = acc[co][qq] + bb;
            v = 1.f / (1.f + __expf(-v));
            out[(((long)n * 3 + co) * 256 + (y0 + ty)) * 256 + (x0 + txq*4 + qq)] = v;
        }
    }
}

// ---------------- host ----------------
static float* symaddr(const void* sym) {
    void* p = nullptr;
    cudaGetSymbolAddress(&p, sym);
    return (float*)p;
}

static Epi mk_row(float* out, const float* bias, int ldc, int act) {
    Epi e; e.out = out; e.bias = bias; e.mode = 0; e.act = act; e.ldc = ldc;
    e.MPN = e.OV = e.W2 = e.C = e.py = e.px = 0; e.nstride = 0; return e;
}
static Epi mk_dec(float* out, const float* bias, int MPN, int OV, int W2, int C,
                  int py, int px, long nstride, int act) {
    Epi e; e.out = out; e.bias = bias; e.mode = 1; e.act = act; e.ldc = 0;
    e.MPN = MPN; e.OV = OV; e.W2 = W2; e.C = C; e.py = py; e.px = px;
    e.nstride = nstride; return e;
}

extern "C" void kernel_launch(void* const* d_in, const int* in_sizes, int n_in,
                              void* d_out, int out_size) {
    const float* x   = (const float*)d_in[0];
    const float* w1  = (const float*)d_in[1];
    const float* b1  = (const float*)d_in[2];
    const float* w2  = (const float*)d_in[3];
    const float* b2  = (const float*)d_in[4];
    const float* w3  = (const float*)d_in[5];
    const float* b3  = (const float*)d_in[6];
    const float* emb = (const float*)d_in[7];
    const float* dw1 = (const float*)d_in[8];
    const float* db1 = (const float*)d_in[9];
    const float* dw2 = (const float*)d_in[10];
    const float* db2 = (const float*)d_in[11];
    const float* dw3 = (const float*)d_in[12];
    const float* db3 = (const float*)d_in[13];
    float* out = (float*)d_out;

    float* xt  = symaddr(g_xt);   float* h1  = symaddr(g_h1);
    float* h2  = symaddr(g_h2);   float* z   = symaddr(g_z);
    float* q   = symaddr(g_q);    float* d1  = symaddr(g_d1);
    float* d2  = symaddr(g_d2);   float* col = symaddr(g_col);
    float* wb1 = symaddr(g_wb1);  float* wb2 = symaddr(g_wb2);
    float* wb3 = symaddr(g_wb3);  float* wbd = symaddr(g_wbd);
    float* en  = symaddr(g_enorm);

    nchw_to_nhwc_x<<<8192, 256>>>(x, xt);
    pack_conv_w<<<(64*48+255)/256, 256>>>(w1, wb1, 64, 3, 4, 4);
    pack_conv_w<<<(128*1024+255)/256, 256>>>(w2, wb2, 128, 64, 4, 4);
    pack_conv_w<<<(64*1152+255)/256, 256>>>(w3, wb3, 64, 128, 3, 3);
    compute_enorm<<<2, 256>>>(emb, en);
    zero_loss<<<1, 1>>>();

    // L1: conv 3->64 k4 s2 p1  (M=524288, K=48, N=64)
    im2col_conv<3,4,4,2,1,256,256,128,16,16><<<524288/16, 256>>>(xt, col);
    sgemm<<<dim3(1, 4096), 256>>>(col, wb1, 48, mk_row(h1, b1, 64, 1));

    // L2: conv 64->128 k4 s2 p1  (M=131072, K=1024, N=128)
    im2col_conv<64,4,4,2,1,128,128,64,64,4><<<131072/4, 256>>>(h1, col);
    sgemm<<<dim3(2, 1024), 256>>>(col, wb2, 1024, mk_row(h2, b2, 128, 1));

    // L3: conv 128->64 k3 s1 p1  (M=131072, K=1152, N=64)
    im2col_conv<128,3,3,1,1,64,64,64,128,2><<<131072/2, 256>>>(h2, col);
    sgemm<<<dim3(1, 1024), 256>>>(col, wb3, 1152, mk_row(z, b3, 64, 1));

    // VQ: scores = z @ emb^T  (M=131072, K=64, N=512) into col; argmin/gather/loss
    sgemm<<<dim3(8, 1024), 256>>>(z, emb, 64, mk_row(col, nullptr, 512, 0));
    vq_kernel<<<131072/8, 256>>>(col, z, emb, en, q);

    // D1: deconv 64->128 k4 s2 p1, 4 parities (M=131072, K=256, N=128)
    for (int py = 0; py < 2; ++py)
        for (int px = 0; px < 2; ++px) {
            pack_deconv_w<<<128, 256>>>(dw1, wbd, 64, 128, py, px);
            im2col_deconv<64,64,64,64,4><<<131072/4, 256>>>(q, col, py, px);
            sgemm<<<dim3(2, 1024), 256>>>(col, wbd, 256,
                mk_dec(d1, db1, 64*64, 64, 128, 128, py, px, (long)128*128*128, 1));
        }

    // D2: deconv 128->64 k4 s2 p1, 4 parities (M=524288, K=512, N=64)
    for (int py = 0; py < 2; ++py)
        for (int px = 0; px < 2; ++px) {
            pack_deconv_w<<<128, 256>>>(dw2, wbd, 128, 64, py, px);
            im2col_deconv<128,128,128,128,2><<<524288/2, 256>>>(d1, col, py, px);
            sgemm<<<dim3(1, 4096), 256>>>(col, wbd, 512,
                mk_dec(d2, db2, 128*128, 128, 256, 64, py, px, (long)256*256*64, 1));
        }

    // D3: deconv 64->3 k3 s1 p1 + sigmoid -> NCHW out
    deconv3_sigmoid<<<dim3(4, 16, 32), 256>>>(d2, dw3, db3, out);

    finalize_loss<<<1, 1>>>(out, (long)out_size - 1);
}

// round 3
// speedup vs baseline: 1.3259x; 1.3259x over previous
#include <cuda_runtime.h>
#include <math.h>

// ---------------- device scratch ----------------
__device__ float  g_xt [6291456];     // x NHWC [32,256,256,3]
__device__ float  g_h1 [33554432];    // [32,128,128,64] NHWC
__device__ float  g_h2 [16777216];    // [32,64,64,128]  NHWC
__device__ float  g_z  [8388608];     // [32,64,64,64]   NHWC == flat [131072,64]
__device__ float  g_q  [8388608];
__device__ float  g_d1 [67108864];    // [32,128,128,128] NHWC
__device__ float  g_d2 [134217728];   // [32,256,256,64]  NHWC
__device__ float  g_col[25165824];    // L1 im2col only: 524288*48
__device__ float  g_wb1[64*48];
__device__ float  g_wb2[128*1024];
__device__ float  g_wb3[64*1152];
__device__ float  g_wbd[32768];
__device__ float  g_enorm[512];
__device__ double g_loss;

// ---------------- small kernels ----------------
__global__ void nchw_to_nhwc_x(const float* __restrict__ in, float* __restrict__ out) {
    int idx = blockIdx.x * 256 + threadIdx.x;            // 32*65536
    int n = idx >> 16, yx = idx & 65535;
    const float* ib = in + (long)n * 196608 + yx;
    float* ob = out + (long)idx * 3;
    ob[0] = ib[0]; ob[1] = ib[65536]; ob[2] = ib[131072];
}

// w[co][ci][ky][kx] -> bw[co][(ky*KW+kx)*Cin+ci]
__global__ void pack_conv_w(const float* __restrict__ w, float* __restrict__ bw,
                            int Cout, int Cin, int KH, int KW) {
    int idx = blockIdx.x * 256 + threadIdx.x;
    int K = Cin * KH * KW;
    if (idx >= Cout * K) return;
    int co = idx / K, rem = idx % K;
    int ci = rem / (KH * KW), r2 = rem % (KH * KW);
    bw[(long)co * K + r2 * Cin + ci] = w[idx];
}

// deconv k4s2p1 parity pack: w[ci][co][4][4] -> bw[co][(ty*2+tx)*Cin+ci], ky=(1-py)+2ty
__global__ void pack_deconv_w(const float* __restrict__ w, float* __restrict__ bw,
                              int Cin, int Cout, int py, int px) {
    int idx = blockIdx.x * 256 + threadIdx.x;
    if (idx >= Cout * Cin * 4) return;
    int co = idx / (Cin * 4), rem = idx % (Cin * 4);
    int ci = rem / 4, tt = rem % 4;
    int ky = (1 - py) + 2 * (tt >> 1), kx = (1 - px) + 2 * (tt & 1);
    bw[(long)co * (4 * Cin) + tt * Cin + ci] = w[(((long)ci * Cout + co) * 4 + ky) * 4 + kx];
}

__global__ void compute_enorm(const float* __restrict__ emb, float* __restrict__ en) {
    int j = blockIdx.x * 256 + threadIdx.x;
    if (j >= 512) return;
    float s = 0.f;
    const float* e = emb + (long)j * 64;
#pragma unroll 8
    for (int d = 0; d < 64; ++d) { float v = e[d]; s = fmaf(v, v, s); }
    en[j] = s;
}

__global__ void zero_loss() { g_loss = 0.0; }
__global__ void finalize_loss(float* out, long pos) {
    out[pos] = (float)(1.25 * g_loss / 8388608.0);
}

// ---------------- explicit im2col (L1 only, CIN=3) ----------------
template<int CIN, int KH, int KW, int ST, int PAD, int IH, int IW, int OW, int KT, int MB>
__global__ void __launch_bounds__(256)
im2col_conv(const float* __restrict__ in, float* __restrict__ col) {
    constexpr int K = KH * KW * CIN;
    int mi = threadIdx.x / KT, kt = threadIdx.x % KT;
    int m = blockIdx.x * MB + mi;
    int n = m / (OW * OW);
    int r = m % (OW * OW);
    int oy = r / OW, ox = r % OW;
    const float* inb = in + (long)n * IH * IW * CIN;
    float* colr = col + (long)m * K;
    for (int k = kt; k < K; k += KT) {
        int ci = k % CIN, t = k / CIN;
        int kx = t % KW, ky = t / KW;
        int iy = oy * ST - PAD + ky, ix = ox * ST - PAD + kx;
        float v = 0.f;
        if (iy >= 0 && iy < IH && ix >= 0 && ix < IW)
            v = inb[((long)iy * IW + ix) * CIN + ci];
        colr[k] = v;
    }
}

// ---------------- A-tile loaders for implicit GEMM ----------------
struct DenseLoader {
    const float* A; int ldk;
    const float* p;
    __device__ void init(int m) { p = A + (long)m * ldk; }
    __device__ void load8(int k, float4& a0, float4& a1) const {
        a0 = *(const float4*)(p + k);
        a1 = *(const float4*)(p + k + 4);
    }
};

// conv: m=(n,oy,ox), k=(ky,kx,ci) ci innermost; requires CIN % 16 == 0
template<int CIN, int KH, int KW, int ST, int PAD, int IH, int IW, int OW>
struct ConvLoader {
    const float* in;
    const float* base; int oy, ox;
    __device__ void init(int m) {
        int n = m / (OW * OW);
        int r = m % (OW * OW);
        oy = r / OW; ox = r % OW;
        base = in + (long)n * IH * IW * CIN;
    }
    __device__ void load8(int k, float4& a0, float4& a1) const {
        int ci = k % CIN, t = k / CIN;
        int ky = t / KW, kx = t % KW;
        int iy = oy * ST - PAD + ky, ix = ox * ST - PAD + kx;
        if (iy >= 0 && iy < IH && ix >= 0 && ix < IW) {
            const float* p = base + ((long)iy * IW + ix) * CIN + ci;
            a0 = *(const float4*)p; a1 = *(const float4*)(p + 4);
        } else {
            a0 = make_float4(0.f,0.f,0.f,0.f); a1 = a0;
        }
    }
};

// deconv k4s2p1 parity: m=(n,u,v), k=(t,ci), t=ty*2+tx, iy=u+py-ty, ix=v+px-tx
template<int CIN, int IH, int IW>
struct DeconvLoader {
    const float* in; int py, px;
    const float* base; int u, v;
    __device__ void init(int m) {
        int n = m / (IH * IW);
        int r = m % (IH * IW);
        u = r / IW; v = r % IW;
        base = in + (long)n * IH * IW * CIN;
    }
    __device__ void load8(int k, float4& a0, float4& a1) const {
        int ci = k % CIN, t = k / CIN;
        int iy = u + py - (t >> 1), ix = v + px - (t & 1);
        if (iy >= 0 && iy < IH && ix >= 0 && ix < IW) {
            const float* p = base + ((long)iy * IW + ix) * CIN + ci;
            a0 = *(const float4*)p; a1 = *(const float4*)(p + 4);
        } else {
            a0 = make_float4(0.f,0.f,0.f,0.f); a1 = a0;
        }
    }
};

// ---------------- SGEMM core: C = A[M,K] * B[N,K]^T ----------------
struct Epi {
    float* out; const float* bias;
    int mode, act, ldc;          // mode 0: row-major; 1: deconv NHWC scatter
    int MPN, OV, W2, C, py, px;
    long nstride;
};

template<class LD>
__global__ void __launch_bounds__(256)
sgemm_t(LD ld, const float* __restrict__ Bm, int K, Epi ep) {
    __shared__ float As[16][132];
    __shared__ float Bs[16][68];
    const int tid = threadIdx.x;
    const int m0 = blockIdx.y * 128, n0 = blockIdx.x * 64;
    const int tx = tid & 15, ty = tid >> 4;
    const int ra = tid >> 1, ca = (tid & 1) * 8;
    const int rb = tid >> 2, cb = (tid & 3) * 4;
    float acc[8][4] = {};
    ld.init(m0 + ra);
    const float* Bptr = Bm + (long)(n0 + rb) * K + cb;

    for (int k0 = 0; k0 < K; k0 += 16) {
        float4 a0, a1;
        ld.load8(k0 + ca, a0, a1);
        float4 b0 = *(const float4*)(Bptr + k0);
        As[ca+0][ra]=a0.x; As[ca+1][ra]=a0.y; As[ca+2][ra]=a0.z; As[ca+3][ra]=a0.w;
        As[ca+4][ra]=a1.x; As[ca+5][ra]=a1.y; As[ca+6][ra]=a1.z; As[ca+7][ra]=a1.w;
        Bs[cb+0][rb]=b0.x; Bs[cb+1][rb]=b0.y; Bs[cb+2][rb]=b0.z; Bs[cb+3][rb]=b0.w;
        __syncthreads();
#pragma unroll
        for (int kk = 0; kk < 16; ++kk) {
            float4 aA = *(const float4*)&As[kk][ty*8];
            float4 aB = *(const float4*)&As[kk][ty*8+4];
            float4 bb = *(const float4*)&Bs[kk][tx*4];
            float av[8] = {aA.x,aA.y,aA.z,aA.w,aB.x,aB.y,aB.z,aB.w};
            float bv[4] = {bb.x,bb.y,bb.z,bb.w};
#pragma unroll
            for (int i = 0; i < 8; ++i)
#pragma unroll
                for (int j = 0; j < 4; ++j)
                    acc[i][j] = fmaf(av[i], bv[j], acc[i][j]);
        }
        __syncthreads();
    }

    const int n_base = n0 + tx * 4;
    float bvals[4];
#pragma unroll
    for (int j = 0; j < 4; ++j) bvals[j] = ep.bias ? ep.bias[n_base + j] : 0.f;
#pragma unroll
    for (int i = 0; i < 8; ++i) {
        int m = m0 + ty * 8 + i;
        long base;
        if (ep.mode == 0) base = (long)m * ep.ldc + n_base;
        else {
            int nn = m / ep.MPN, r = m % ep.MPN;
            int u = r / ep.OV, v = r % ep.OV;
            base = (long)nn * ep.nstride +
                   ((long)(2*u + ep.py) * ep.W2 + (2*v + ep.px)) * ep.C + n_base;
        }
#pragma unroll
        for (int j = 0; j < 4; ++j) {
            float vv = acc[i][j] + bvals[j];
            if (ep.act) vv = fmaxf(vv, 0.f);
            ep.out[base + j] = vv;
        }
    }
}

// ---------------- fused VQ: distances + argmin + gather + loss ----------------
__global__ void __launch_bounds__(256)
vq_fused(const float* __restrict__ z, const float* __restrict__ emb,
         const float* __restrict__ enorm, float* __restrict__ q) {
    __shared__ float4 se[16][16];   // 16 codes x 64 floats
    __shared__ float sen[16];
    __shared__ float red[256];
    const int t = threadIdx.x;
    const long m = (long)blockIdx.x * 256 + t;
    float4 zr[16];
    const float4* zp = (const float4*)(z + m * 64);
#pragma unroll
    for (int i = 0; i < 16; ++i) zr[i] = zp[i];

    float best = 3.4e38f; int bidx = 0;
    const int ljj = t >> 4, ldd = t & 15;
    for (int j0 = 0; j0 < 512; j0 += 16) {
        __syncthreads();
        se[ljj][ldd] = ((const float4*)(emb + (long)(j0 + ljj) * 64))[ldd];
        if (t < 16) sen[t] = enorm[j0 + t];
        __syncthreads();
#pragma unroll
        for (int jj = 0; jj < 16; ++jj) {
            float s0 = 0.f, s1 = 0.f, s2 = 0.f, s3 = 0.f;
#pragma unroll
            for (int d = 0; d < 16; d += 4) {
                float4 e0 = se[jj][d+0], e1 = se[jj][d+1];
                float4 e2 = se[jj][d+2], e3 = se[jj][d+3];
                s0 = fmaf(zr[d+0].x, e0.x, s0); s0 = fmaf(zr[d+0].y, e0.y, s0);
                s0 = fmaf(zr[d+0].z, e0.z, s0); s0 = fmaf(zr[d+0].w, e0.w, s0);
                s1 = fmaf(zr[d+1].x, e1.x, s1); s1 = fmaf(zr[d+1].y, e1.y, s1);
                s1 = fmaf(zr[d+1].z, e1.z, s1); s1 = fmaf(zr[d+1].w, e1.w, s1);
                s2 = fmaf(zr[d+2].x, e2.x, s2); s2 = fmaf(zr[d+2].y, e2.y, s2);
                s2 = fmaf(zr[d+2].z, e2.z, s2); s2 = fmaf(zr[d+2].w, e2.w, s2);
                s3 = fmaf(zr[d+3].x, e3.x, s3); s3 = fmaf(zr[d+3].y, e3.y, s3);
                s3 = fmaf(zr[d+3].z, e3.z, s3); s3 = fmaf(zr[d+3].w, e3.w, s3);
            }
            float dist = sen[jj] - 2.f * ((s0 + s1) + (s2 + s3));
            if (dist < best) { best = dist; bidx = j0 + jj; }
        }
    }

    // gather q row + per-row squared diff
    const float4* ep = (const float4*)(emb + (long)bidx * 64);
    float4* qp = (float4*)(q + m * 64);
    float sq = 0.f;
#pragma unroll
    for (int i = 0; i < 16; ++i) {
        float4 e = ep[i];
        qp[i] = e;
        float d0 = e.x - zr[i].x, d1 = e.y - zr[i].y;
        float d2 = e.z - zr[i].z, d3 = e.w - zr[i].w;
        sq = fmaf(d0, d0, sq); sq = fmaf(d1, d1, sq);
        sq = fmaf(d2, d2, sq); sq = fmaf(d3, d3, sq);
    }
    red[t] = sq;
    __syncthreads();
    for (int s = 128; s; s >>= 1) {
        if (t < s) red[t] += red[t + s];
        __syncthreads();
    }
    if (t == 0) atomicAdd(&g_loss, (double)red[0]);
}

// ---------------- final deconv 64->3 k3 s1 p1 + sigmoid (direct, NCHW out) ----------------
__global__ void __launch_bounds__(256)
deconv3_sigmoid(const float* __restrict__ in, const float* __restrict__ w,
                const float* __restrict__ bias, float* __restrict__ out) {
    __shared__ float sIn[8][18][66];
    __shared__ float sW[1728];
    const int t = threadIdx.x, n = blockIdx.z;
    const int y0 = blockIdx.y * 16, x0 = blockIdx.x * 64;
    for (int i = t; i < 1728; i += 256) sW[i] = w[i];
    const int ty = t >> 4, txq = t & 15;
    float acc[3][4] = {};
    for (int cc = 0; cc < 8; ++cc) {
        __syncthreads();
        for (int idx = t; idx < 8*18*66; idx += 256) {
            int ci = idx & 7, rr = idx >> 3;
            int sx = rr % 66, sy = rr / 66;
            int gy = y0 - 1 + sy, gx = x0 - 1 + sx;
            float v = 0.f;
            if (gy >= 0 && gy < 256 && gx >= 0 && gx < 256)
                v = in[(((long)n * 256 + gy) * 256 + gx) * 64 + cc * 8 + ci];
            sIn[ci][sy][sx] = v;
        }
        __syncthreads();
#pragma unroll
        for (int c8 = 0; c8 < 8; ++c8) {
            const int ci = cc * 8 + c8;
#pragma unroll
            for (int ky = 0; ky < 3; ++ky)
#pragma unroll
            for (int kx = 0; kx < 3; ++kx) {
                const float* wp = &sW[ci*27 + ky*3 + kx];
                float w0 = wp[0], w1 = wp[9], w2 = wp[18];
                const float* ip = &sIn[c8][ty + 2 - ky][txq*4 + 2 - kx];
#pragma unroll
                for (int qq = 0; qq < 4; ++qq) {
                    float iv = ip[qq];
                    acc[0][qq] = fmaf(iv, w0, acc[0][qq]);
                    acc[1][qq] = fmaf(iv, w1, acc[1][qq]);
                    acc[2][qq] = fmaf(iv, w2, acc[2][qq]);
                }
            }
        }
    }
#pragma unroll
    for (int co = 0; co < 3; ++co) {
        float bb = bias[co];
#pragma unroll
        for (int qq = 0; qq < 4; ++qq) {
            float v = acc[co][qq] + bb;
            v = 1.f / (1.f + __expf(-v));
            out[(((long)n * 3 + co) * 256 + (y0 + ty)) * 256 + (x0 + txq*4 + qq)] = v;
        }
    }
}

// ---------------- host ----------------
static float* symaddr(const void* sym) {
    void* p = nullptr;
    cudaGetSymbolAddress(&p, sym);
    return (float*)p;
}

static Epi mk_row(float* out, const float* bias, int ldc, int act) {
    Epi e; e.out = out; e.bias = bias; e.mode = 0; e.act = act; e.ldc = ldc;
    e.MPN = e.OV = e.W2 = e.C = e.py = e.px = 0; e.nstride = 0; return e;
}
static Epi mk_dec(float* out, const float* bias, int MPN, int OV, int W2, int C,
                  int py, int px, long nstride, int act) {
    Epi e; e.out = out; e.bias = bias; e.mode = 1; e.act = act; e.ldc = 0;
    e.MPN = MPN; e.OV = OV; e.W2 = W2; e.C = C; e.py = py; e.px = px;
    e.nstride = nstride; return e;
}

extern "C" void kernel_launch(void* const* d_in, const int* in_sizes, int n_in,
                              void* d_out, int out_size) {
    const float* x   = (const float*)d_in[0];
    const float* w1  = (const float*)d_in[1];
    const float* b1  = (const float*)d_in[2];
    const float* w2  = (const float*)d_in[3];
    const float* b2  = (const float*)d_in[4];
    const float* w3  = (const float*)d_in[5];
    const float* b3  = (const float*)d_in[6];
    const float* emb = (const float*)d_in[7];
    const float* dw1 = (const float*)d_in[8];
    const float* db1 = (const float*)d_in[9];
    const float* dw2 = (const float*)d_in[10];
    const float* db2 = (const float*)d_in[11];
    const float* dw3 = (const float*)d_in[12];
    const float* db3 = (const float*)d_in[13];
    float* out = (float*)d_out;

    float* xt  = symaddr(g_xt);   float* h1  = symaddr(g_h1);
    float* h2  = symaddr(g_h2);   float* z   = symaddr(g_z);
    float* q   = symaddr(g_q);    float* d1  = symaddr(g_d1);
    float* d2  = symaddr(g_d2);   float* col = symaddr(g_col);
    float* wb1 = symaddr(g_wb1);  float* wb2 = symaddr(g_wb2);
    float* wb3 = symaddr(g_wb3);  float* wbd = symaddr(g_wbd);
    float* en  = symaddr(g_enorm);

    nchw_to_nhwc_x<<<8192, 256>>>(x, xt);
    pack_conv_w<<<(64*48+255)/256, 256>>>(w1, wb1, 64, 3, 4, 4);
    pack_conv_w<<<(128*1024+255)/256, 256>>>(w2, wb2, 128, 64, 4, 4);
    pack_conv_w<<<(64*1152+255)/256, 256>>>(w3, wb3, 64, 128, 3, 3);
    compute_enorm<<<2, 256>>>(emb, en);
    zero_loss<<<1, 1>>>();

    // L1: conv 3->64 k4 s2 p1 (M=524288, K=48, N=64): explicit col + dense GEMM
    im2col_conv<3,4,4,2,1,256,256,128,16,16><<<524288/16, 256>>>(xt, col);
    { DenseLoader ld; ld.A = col; ld.ldk = 48;
      sgemm_t<<<dim3(1, 4096), 256>>>(ld, wb1, 48, mk_row(h1, b1, 64, 1)); }

    // L2: conv 64->128 k4 s2 p1 (M=131072, K=1024, N=128), implicit
    { ConvLoader<64,4,4,2,1,128,128,64> ld; ld.in = h1;
      sgemm_t<<<dim3(2, 1024), 256>>>(ld, wb2, 1024, mk_row(h2, b2, 128, 1)); }

    // L3: conv 128->64 k3 s1 p1 (M=131072, K=1152, N=64), implicit
    { ConvLoader<128,3,3,1,1,64,64,64> ld; ld.in = h2;
      sgemm_t<<<dim3(1, 1024), 256>>>(ld, wb3, 1152, mk_row(z, b3, 64, 1)); }

    // VQ fused: distances + argmin + gather + loss
    vq_fused<<<512, 256>>>(z, emb, en, q);

    // D1: deconv 64->128 k4 s2 p1, 4 parities (M=131072, K=256, N=128), implicit
    for (int py = 0; py < 2; ++py)
        for (int px = 0; px < 2; ++px) {
            pack_deconv_w<<<128, 256>>>(dw1, wbd, 64, 128, py, px);
            DeconvLoader<64,64,64> ld; ld.in = q; ld.py = py; ld.px = px;
            sgemm_t<<<dim3(2, 1024), 256>>>(ld, wbd, 256,
                mk_dec(d1, db1, 64*64, 64, 128, 128, py, px, (long)128*128*128, 1));
        }

    // D2: deconv 128->64 k4 s2 p1, 4 parities (M=524288, K=512, N=64), implicit
    for (int py = 0; py < 2; ++py)
        for (int px = 0; px < 2; ++px) {
            pack_deconv_w<<<128, 256>>>(dw2, wbd, 128, 64, py, px);
            DeconvLoader<128,128,128> ld; ld.in = d1; ld.py = py; ld.px = px;
            sgemm_t<<<dim3(1, 4096), 256>>>(ld, wbd, 512,
                mk_dec(d2, db2, 128*128, 128, 256, 64, py, px, (long)256*256*64, 1));
        }

    // D3: deconv 64->3 k3 s1 p1 + sigmoid -> NCHW out
    deconv3_sigmoid<<<dim3(4, 16, 32), 256>>>(d2, dw3, db3, out);

    finalize_loss<<<1, 1>>>(out, (long)out_size - 1);
}

// round 6
// speedup vs baseline: 2.1339x; 1.6093x over previous
#include <cuda_runtime.h>
#include <cuda_bf16.h>
#include <cstdint>
#include <math.h>

// ---------------- device scratch ----------------
__device__ float  g_xt [6291456];     // x NHWC [32,256,256,3]
__device__ float  g_h1 [33554432];    // [32,128,128,64] NHWC
__device__ float  g_h2 [16777216];    // [32,64,64,128]  NHWC
__device__ float  g_z  [8388608];     // [32,64,64,64]   NHWC == flat [131072,64]
__device__ float  g_q  [8388608];
__device__ float  g_d1 [67108864];    // [32,128,128,128] NHWC
__device__ float  g_d2 [134217728];   // [32,256,256,64]  NHWC
__device__ float  g_col[25165824];    // L1 im2col only
__device__ float  g_wb1[64*48];
__device__ float  g_wb2[128*1024];
__device__ float  g_wb3[64*1152];
__device__ __nv_bfloat16 g_wbd[32768];
__device__ float  g_enorm[512];
__device__ double g_loss;

__device__ __forceinline__ uint32_t smem_u32(const void* p) {
    uint32_t a;
    asm("{ .reg .u64 t; cvta.to.shared.u64 t, %1; cvt.u32.u64 %0, t; }" : "=r"(a) : "l"(p));
    return a;
}
__device__ __forceinline__ uint32_t swz(uint32_t off) { return off ^ ((off >> 3) & 0x70); }

// ---------------- small kernels ----------------
__global__ void nchw_to_nhwc_x(const float* __restrict__ in, float* __restrict__ out) {
    int idx = blockIdx.x * 256 + threadIdx.x;            // 32*65536
    int n = idx >> 16, yx = idx & 65535;
    const float* ib = in + (long)n * 196608 + yx;
    float* ob = out + (long)idx * 3;
    ob[0] = ib[0]; ob[1] = ib[65536]; ob[2] = ib[131072];
}

// w[co][ci][ky][kx] -> bw[co][(ky*KW+kx)*Cin+ci]  (fp32, encoder)
__global__ void pack_conv_w(const float* __restrict__ w, float* __restrict__ bw,
                            int Cout, int Cin, int KH, int KW) {
    int idx = blockIdx.x * 256 + threadIdx.x;
    int K = Cin * KH * KW;
    if (idx >= Cout * K) return;
    int co = idx / K, rem = idx % K;
    int ci = rem / (KH * KW), r2 = rem % (KH * KW);
    bw[(long)co * K + r2 * Cin + ci] = w[idx];
}

// deconv k4s2p1 parity pack -> bf16: w[ci][co][4][4] -> bw[co][(ty*2+tx)*Cin+ci]
__global__ void pack_deconv_w_bf16(const float* __restrict__ w, __nv_bfloat16* __restrict__ bw,
                                   int Cin, int Cout, int py, int px) {
    int idx = blockIdx.x * 256 + threadIdx.x;
    if (idx >= Cout * Cin * 4) return;
    int co = idx / (Cin * 4), rem = idx % (Cin * 4);
    int ci = rem / 4, tt = rem % 4;
    int ky = (1 - py) + 2 * (tt >> 1), kx = (1 - px) + 2 * (tt & 1);
    bw[(long)co * (4 * Cin) + tt * Cin + ci] =
        __float2bfloat16(w[(((long)ci * Cout + co) * 4 + ky) * 4 + kx]);
}

__global__ void compute_enorm(const float* __restrict__ emb, float* __restrict__ en) {
    int j = blockIdx.x * 256 + threadIdx.x;
    if (j >= 512) return;
    float s = 0.f;
    const float* e = emb + (long)j * 64;
#pragma unroll 8
    for (int d = 0; d < 64; ++d) { float v = e[d]; s = fmaf(v, v, s); }
    en[j] = s;
}

__global__ void zero_loss() { g_loss = 0.0; }
__global__ void finalize_loss(float* out, long pos) {
    out[pos] = (float)(1.25 * g_loss / 8388608.0);
}

// ---------------- explicit im2col (L1 only, CIN=3) ----------------
template<int CIN, int KH, int KW, int ST, int PAD, int IH, int IW, int OW, int KT, int MB>
__global__ void __launch_bounds__(256)
im2col_conv(const float* __restrict__ in, float* __restrict__ col) {
    constexpr int K = KH * KW * CIN;
    int mi = threadIdx.x / KT, kt = threadIdx.x % KT;
    int m = blockIdx.x * MB + mi;
    int n = m / (OW * OW);
    int r = m % (OW * OW);
    int oy = r / OW, ox = r % OW;
    const float* inb = in + (long)n * IH * IW * CIN;
    float* colr = col + (long)m * K;
    for (int k = kt; k < K; k += KT) {
        int ci = k % CIN, t = k / CIN;
        int kx = t % KW, ky = t / KW;
        int iy = oy * ST - PAD + ky, ix = ox * ST - PAD + kx;
        float v = 0.f;
        if (iy >= 0 && iy < IH && ix >= 0 && ix < IW)
            v = inb[((long)iy * IW + ix) * CIN + ci];
        colr[k] = v;
    }
}

// ---------------- A-tile loaders ----------------
struct DenseLoader {
    const float* A; int ldk;
    const float* p;
    __device__ void init(int m) { p = A + (long)m * ldk; }
    __device__ void load8(int k, float4& a0, float4& a1) const {
        a0 = *(const float4*)(p + k);
        a1 = *(const float4*)(p + k + 4);
    }
};

template<int CIN, int KH, int KW, int ST, int PAD, int IH, int IW, int OW>
struct ConvLoader {
    const float* in;
    const float* base; int oy, ox;
    __device__ void init(int m) {
        int n = m / (OW * OW);
        int r = m % (OW * OW);
        oy = r / OW; ox = r % OW;
        base = in + (long)n * IH * IW * CIN;
    }
    __device__ void load8(int k, float4& a0, float4& a1) const {
        int ci = k % CIN, t = k / CIN;
        int ky = t / KW, kx = t % KW;
        int iy = oy * ST - PAD + ky, ix = ox * ST - PAD + kx;
        if (iy >= 0 && iy < IH && ix >= 0 && ix < IW) {
            const float* p = base + ((long)iy * IW + ix) * CIN + ci;
            a0 = *(const float4*)p; a1 = *(const float4*)(p + 4);
        } else {
            a0 = make_float4(0.f,0.f,0.f,0.f); a1 = a0;
        }
    }
};

template<int CIN, int IH, int IW>
struct DeconvLoader {
    const float* in; int py, px;
    const float* base; int u, v;
    __device__ void init(int m) {
        int n = m / (IH * IW);
        int r = m % (IH * IW);
        u = r / IW; v = r % IW;
        base = in + (long)n * IH * IW * CIN;
    }
    // 32 contiguous k-values, guaranteed within one tap (CIN % 32 == 0)
    __device__ void load32(int k, float4 (&a)[8]) const {
        int ci = k % CIN, t = k / CIN;
        int iy = u + py - (t >> 1), ix = v + px - (t & 1);
        if (iy >= 0 && iy < IH && ix >= 0 && ix < IW) {
            const float4* p = (const float4*)(base + ((long)iy * IW + ix) * CIN + ci);
#pragma unroll
            for (int i = 0; i < 8; ++i) a[i] = p[i];
        } else {
#pragma unroll
            for (int i = 0; i < 8; ++i) a[i] = make_float4(0.f,0.f,0.f,0.f);
        }
    }
};

// ---------------- epilogue descriptor ----------------
struct Epi {
    float* out; const float* bias;
    int mode, act, ldc;          // mode 0: row-major; 1: deconv NHWC scatter
    int MPN, OV, W2, C, py, px;
    long nstride;
};

__device__ __forceinline__ long epi_base(const Epi& ep, int m) {
    if (ep.mode == 0) return (long)m * ep.ldc;
    int nn = m / ep.MPN, r = m % ep.MPN;
    int u = r / ep.OV, v = r % ep.OV;
    return (long)nn * ep.nstride +
           ((long)(2*u + ep.py) * ep.W2 + (2*v + ep.px)) * ep.C;
}

// ---------------- fp32 SGEMM (encoder): C = A[M,K] * B[N,K]^T ----------------
template<class LD>
__global__ void __launch_bounds__(256)
sgemm_t(LD ld, const float* __restrict__ Bm, int K, Epi ep) {
    __shared__ float As[16][132];
    __shared__ float Bs[16][68];
    const int tid = threadIdx.x;
    const int m0 = blockIdx.y * 128, n0 = blockIdx.x * 64;
    const int tx = tid & 15, ty = tid >> 4;
    const int ra = tid >> 1, ca = (tid & 1) * 8;
    const int rb = tid >> 2, cb = (tid & 3) * 4;
    float acc[8][4] = {};
    ld.init(m0 + ra);
    const float* Bptr = Bm + (long)(n0 + rb) * K + cb;

    for (int k0 = 0; k0 < K; k0 += 16) {
        float4 a0, a1;
        ld.load8(k0 + ca, a0, a1);
        float4 b0 = *(const float4*)(Bptr + k0);
        As[ca+0][ra]=a0.x; As[ca+1][ra]=a0.y; As[ca+2][ra]=a0.z; As[ca+3][ra]=a0.w;
        As[ca+4][ra]=a1.x; As[ca+5][ra]=a1.y; As[ca+6][ra]=a1.z; As[ca+7][ra]=a1.w;
        Bs[cb+0][rb]=b0.x; Bs[cb+1][rb]=b0.y; Bs[cb+2][rb]=b0.z; Bs[cb+3][rb]=b0.w;
        __syncthreads();
#pragma unroll
        for (int kk = 0; kk < 16; ++kk) {
            float4 aA = *(const float4*)&As[kk][ty*8];
            float4 aB = *(const float4*)&As[kk][ty*8+4];
            float4 bb = *(const float4*)&Bs[kk][tx*4];
            float av[8] = {aA.x,aA.y,aA.z,aA.w,aB.x,aB.y,aB.z,aB.w};
            float bv[4] = {bb.x,bb.y,bb.z,bb.w};
#pragma unroll
            for (int i = 0; i < 8; ++i)
#pragma unroll
                for (int j = 0; j < 4; ++j)
                    acc[i][j] = fmaf(av[i], bv[j], acc[i][j]);
        }
        __syncthreads();
    }

    const int n_base = n0 + tx * 4;
    float bvals[4];
#pragma unroll
    for (int j = 0; j < 4; ++j) bvals[j] = ep.bias ? ep.bias[n_base + j] : 0.f;
#pragma unroll
    for (int i = 0; i < 8; ++i) {
        int m = m0 + ty * 8 + i;
        long base = (long)m * ep.ldc + n_base;
#pragma unroll
        for (int j = 0; j < 4; ++j) {
            float vv = acc[i][j] + bvals[j];
            if (ep.act) vv = fmaxf(vv, 0.f);
            ep.out[base + j] = vv;
        }
    }
}

// ---------------- HMMA bf16 GEMM (decoder): C = A[M,K] * B[N,K]^T ----------------
// Block tile 128 x TN, 8 warps as 4(m) x 2(n); warp tile 32 x TN/2. K-chunk 64.
// A fp32 -> bf16 converted on the fly by loader; B pre-packed bf16.
template<class LD, int TN>
__global__ void __launch_bounds__(256)
hgemm(LD ld, const __nv_bfloat16* __restrict__ Bw, int K, Epi ep) {
    constexpr int WN  = TN / 2;       // warp n extent (32 or 64)
    constexpr int NT8 = WN / 8;       // n8 tiles per warp (4 or 8)
    constexpr int NT16 = NT8 / 2;     // n16 ldmatrix groups (2 or 4)
    __shared__ __align__(16) __nv_bfloat16 sA[128 * 64];
    __shared__ __align__(16) __nv_bfloat16 sB[TN * 64];
    const int tid = threadIdx.x;
    const int wid = tid >> 5, lane = tid & 31;
    const int m0 = blockIdx.y * 128;
    const int wm = (wid >> 1) * 32;
    const int wn = (wid & 1) * WN;
    const uint32_t sA0 = smem_u32(sA), sB0 = smem_u32(sB);

    const int row = tid >> 1, half = tid & 1;
    ld.init(m0 + row);

    float acc[2][NT8][4];
#pragma unroll
    for (int i = 0; i < 2; ++i)
#pragma unroll
        for (int j = 0; j < NT8; ++j)
#pragma unroll
            for (int c = 0; c < 4; ++c) acc[i][j][c] = 0.f;

    for (int k0 = 0; k0 < K; k0 += 64) {
        // A fill: thread covers row 'row', 32 k-values
        float4 a[8];
        ld.load32(k0 + half * 32, a);
#pragma unroll
        for (int j = 0; j < 4; ++j) {
            __nv_bfloat162 p0 = __floats2bfloat162_rn(a[2*j].x,   a[2*j].y);
            __nv_bfloat162 p1 = __floats2bfloat162_rn(a[2*j].z,   a[2*j].w);
            __nv_bfloat162 p2 = __floats2bfloat162_rn(a[2*j+1].x, a[2*j+1].y);
            __nv_bfloat162 p3 = __floats2bfloat162_rn(a[2*j+1].z, a[2*j+1].w);
            uint4 u;
            u.x = *(uint32_t*)&p0; u.y = *(uint32_t*)&p1;
            u.z = *(uint32_t*)&p2; u.w = *(uint32_t*)&p3;
            uint32_t off = row * 128 + half * 64 + j * 16;
            *(uint4*)((char*)sA + swz(off)) = u;
        }
        // B fill: TN rows x 64 bf16
        for (int i = tid; i < TN * 8; i += 256) {
            int br = i >> 3, seg = i & 7;
            uint4 u = *(const uint4*)(Bw + (long)br * K + k0 + seg * 8);
            uint32_t off = br * 128 + seg * 16;
            *(uint4*)((char*)sB + swz(off)) = u;
        }
        __syncthreads();
#pragma unroll
        for (int ks = 0; ks < 4; ++ks) {
            uint32_t af[2][4];
#pragma unroll
            for (int mi = 0; mi < 2; ++mi) {
                uint32_t r = wm + mi * 16 + (lane & 15);
                uint32_t kb = ks * 32 + (lane >> 4) * 16;
                uint32_t ad = sA0 + swz(r * 128 + kb);
                asm volatile("ldmatrix.sync.aligned.m8n8.x4.shared.b16 {%0,%1,%2,%3}, [%4];"
                    : "=r"(af[mi][0]), "=r"(af[mi][1]), "=r"(af[mi][2]), "=r"(af[mi][3])
                    : "r"(ad));
            }
            uint32_t bf[NT16][4];
#pragma unroll
            for (int ni = 0; ni < NT16; ++ni) {
                uint32_t r = wn + ni * 16 + (lane & 15);
                uint32_t kb = ks * 32 + (lane >> 4) * 16;
                uint32_t ad = sB0 + swz(r * 128 + kb);
                asm volatile("ldmatrix.sync.aligned.m8n8.x4.shared.b16 {%0,%1,%2,%3}, [%4];"
                    : "=r"(bf[ni][0]), "=r"(bf[ni][1]), "=r"(bf[ni][2]), "=r"(bf[ni][3])
                    : "r"(ad));
            }
#pragma unroll
            for (int mi = 0; mi < 2; ++mi)
#pragma unroll
                for (int ni = 0; ni < NT16; ++ni) {
                    asm volatile(
                        "mma.sync.aligned.m16n8k16.row.col.f32.bf16.bf16.f32 "
                        "{%0,%1,%2,%3}, {%4,%5,%6,%7}, {%8,%9}, {%0,%1,%2,%3};"
                        : "+f"(acc[mi][2*ni][0]), "+f"(acc[mi][2*ni][1]),
                          "+f"(acc[mi][2*ni][2]), "+f"(acc[mi][2*ni][3])
                        : "r"(af[mi][0]), "r"(af[mi][1]), "r"(af[mi][2]), "r"(af[mi][3]),
                          "r"(bf[ni][0]), "r"(bf[ni][2]));
                    asm volatile(
                        "mma.sync.aligned.m16n8k16.row.col.f32.bf16.bf16.f32 "
                        "{%0,%1,%2,%3}, {%4,%5,%6,%7}, {%8,%9}, {%0,%1,%2,%3};"
                        : "+f"(acc[mi][2*ni+1][0]), "+f"(acc[mi][2*ni+1][1]),
                          "+f"(acc[mi][2*ni+1][2]), "+f"(acc[mi][2*ni+1][3])
                        : "r"(af[mi][0]), "r"(af[mi][1]), "r"(af[mi][2]), "r"(af[mi][3]),
                          "r"(bf[ni][1]), "r"(bf[ni][3]));
                }
        }
        __syncthreads();
    }

    // epilogue: fragment c0,c1 at (row, col),(row,col+1); c2,c3 at (row+8, ...)
    const int col = wn + (lane & 3) * 2;
#pragma unroll
    for (int mi = 0; mi < 2; ++mi) {
        int m1 = m0 + wm + mi * 16 + (lane >> 2);
        long b1 = epi_base(ep, m1);
        long b2 = epi_base(ep, m1 + 8);
#pragma unroll
        for (int j = 0; j < NT8; ++j) {
            int n = col + j * 8;
            float bi0 = ep.bias[n], bi1 = ep.bias[n + 1];
            float v0 = acc[mi][j][0] + bi0, v1 = acc[mi][j][1] + bi1;
            float v2 = acc[mi][j][2] + bi0, v3 = acc[mi][j][3] + bi1;
            if (ep.act) {
                v0 = fmaxf(v0, 0.f); v1 = fmaxf(v1, 0.f);
                v2 = fmaxf(v2, 0.f); v3 = fmaxf(v3, 0.f);
            }
            *(float2*)(ep.out + b1 + n) = make_float2(v0, v1);
            *(float2*)(ep.out + b2 + n) = make_float2(v2, v3);
        }
    }
}

// ---------------- fused VQ: distances + argmin + gather + loss ----------------
__global__ void __launch_bounds__(256)
vq_fused(const float* __restrict__ z, const float* __restrict__ emb,
         const float* __restrict__ enorm, float* __restrict__ q) {
    __shared__ float4 se[16][16];
    __shared__ float sen[16];
    __shared__ float red[256];
    const int t = threadIdx.x;
    const long m = (long)blockIdx.x * 256 + t;
    float4 zr[16];
    const float4* zp = (const float4*)(z + m * 64);
#pragma unroll
    for (int i = 0; i < 16; ++i) zr[i] = zp[i];

    float best = 3.4e38f; int bidx = 0;
    const int ljj = t >> 4, ldd = t & 15;
    for (int j0 = 0; j0 < 512; j0 += 16) {
        __syncthreads();
        se[ljj][ldd] = ((const float4*)(emb + (long)(j0 + ljj) * 64))[ldd];
        if (t < 16) sen[t] = enorm[j0 + t];
        __syncthreads();
#pragma unroll
        for (int jj = 0; jj < 16; ++jj) {
            float s0 = 0.f, s1 = 0.f, s2 = 0.f, s3 = 0.f;
#pragma unroll
            for (int d = 0; d < 16; d += 4) {
                float4 e0 = se[jj][d+0], e1 = se[jj][d+1];
                float4 e2 = se[jj][d+2], e3 = se[jj][d+3];
                s0 = fmaf(zr[d+0].x, e0.x, s0); s0 = fmaf(zr[d+0].y, e0.y, s0);
                s0 = fmaf(zr[d+0].z, e0.z, s0); s0 = fmaf(zr[d+0].w, e0.w, s0);
                s1 = fmaf(zr[d+1].x, e1.x, s1); s1 = fmaf(zr[d+1].y, e1.y, s1);
                s1 = fmaf(zr[d+1].z, e1.z, s1); s1 = fmaf(zr[d+1].w, e1.w, s1);
                s2 = fmaf(zr[d+2].x, e2.x, s2); s2 = fmaf(zr[d+2].y, e2.y, s2);
                s2 = fmaf(zr[d+2].z, e2.z, s2); s2 = fmaf(zr[d+2].w, e2.w, s2);
                s3 = fmaf(zr[d+3].x, e3.x, s3); s3 = fmaf(zr[d+3].y, e3.y, s3);
                s3 = fmaf(zr[d+3].z, e3.z, s3); s3 = fmaf(zr[d+3].w, e3.w, s3);
            }
            float dist = sen[jj] - 2.f * ((s0 + s1) + (s2 + s3));
            if (dist < best) { best = dist; bidx = j0 + jj; }
        }
    }

    const float4* ep = (const float4*)(emb + (long)bidx * 64);
    float4* qp = (float4*)(q + m * 64);
    float sq = 0.f;
#pragma unroll
    for (int i = 0; i < 16; ++i) {
        float4 e = ep[i];
        qp[i] = e;
        float d0 = e.x - zr[i].x, d1 = e.y - zr[i].y;
        float d2 = e.z - zr[i].z, d3 = e.w - zr[i].w;
        sq = fmaf(d0, d0, sq); sq = fmaf(d1, d1, sq);
        sq = fmaf(d2, d2, sq); sq = fmaf(d3, d3, sq);
    }
    red[t] = sq;
    __syncthreads();
    for (int s = 128; s; s >>= 1) {
        if (t < s) red[t] += red[t + s];
        __syncthreads();
    }
    if (t == 0) atomicAdd(&g_loss, (double)red[0]);
}

// ---------------- final deconv 64->3 k3 s1 p1 + sigmoid (direct, NCHW out) ----------------
__global__ void __launch_bounds__(256)
deconv3_sigmoid(const float* __restrict__ in, const float* __restrict__ w,
                const float* __restrict__ bias, float* __restrict__ out) {
    __shared__ float sIn[8][18][66];
    __shared__ float sW[1728];
    const int t = threadIdx.x, n = blockIdx.z;
    const int y0 = blockIdx.y * 16, x0 = blockIdx.x * 64;
    for (int i = t; i < 1728; i += 256) sW[i] = w[i];
    const int ty = t >> 4, txq = t & 15;
    float acc[3][4] = {};
    for (int cc = 0; cc < 8; ++cc) {
        __syncthreads();
        for (int idx = t; idx < 8*18*66; idx += 256) {
            int ci = idx & 7, rr = idx >> 3;
            int sx = rr % 66, sy = rr / 66;
            int gy = y0 - 1 + sy, gx = x0 - 1 + sx;
            float v = 0.f;
            if (gy >= 0 && gy < 256 && gx >= 0 && gx < 256)
                v = in[(((long)n * 256 + gy) * 256 + gx) * 64 + cc * 8 + ci];
            sIn[ci][sy][sx] = v;
        }
        __syncthreads();
#pragma unroll
        for (int c8 = 0; c8 < 8; ++c8) {
            const int ci = cc * 8 + c8;
#pragma unroll
            for (int ky = 0; ky < 3; ++ky)
#pragma unroll
            for (int kx = 0; kx < 3; ++kx) {
                const float* wp = &sW[ci*27 + ky*3 + kx];
                float w0 = wp[0], w1 = wp[9], w2 = wp[18];
                const float* ip = &sIn[c8][ty + 2 - ky][txq*4 + 2 - kx];
#pragma unroll
                for (int qq = 0; qq < 4; ++qq) {
                    float iv = ip[qq];
                    acc[0][qq] = fmaf(iv, w0, acc[0][qq]);
                    acc[1][qq] = fmaf(iv, w1, acc[1][qq]);
                    acc[2][qq] = fmaf(iv, w2, acc[2][qq]);
                }
            }
        }
    }
#pragma unroll
    for (int co = 0; co < 3; ++co) {
        float bb = bias[co];
#pragma unroll
        for (int qq = 0; qq < 4; ++qq) {
            float v = acc[co][qq] + bb;
            v = 1.f / (1.f + __expf(-v));
            out[(((long)n * 3 + co) * 256 + (y0 + ty)) * 256 + (x0 + txq*4 + qq)] = v;
        }
    }
}

// ---------------- host ----------------
static float* symaddr(const void* sym) {
    void* p = nullptr;
    cudaGetSymbolAddress(&p, sym);
    return (float*)p;
}

static Epi mk_row(float* out, const float* bias, int ldc, int act) {
    Epi e; e.out = out; e.bias = bias; e.mode = 0; e.act = act; e.ldc = ldc;
    e.MPN = e.OV = e.W2 = e.C = e.py = e.px = 0; e.nstride = 0; return e;
}
static Epi mk_dec(float* out, const float* bias, int MPN, int OV, int W2, int C,
                  int py, int px, long nstride, int act) {
    Epi e; e.out = out; e.bias = bias; e.mode = 1; e.act = act; e.ldc = 0;
    e.MPN = MPN; e.OV = OV; e.W2 = W2; e.C = C; e.py = py; e.px = px;
    e.nstride = nstride; return e;
}

extern "C" void kernel_launch(void* const* d_in, const int* in_sizes, int n_in,
                              void* d_out, int out_size) {
    const float* x   = (const float*)d_in[0];
    const float* w1  = (const float*)d_in[1];
    const float* b1  = (const float*)d_in[2];
    const float* w2  = (const float*)d_in[3];
    const float* b2  = (const float*)d_in[4];
    const float* w3  = (const float*)d_in[5];
    const float* b3  = (const float*)d_in[6];
    const float* emb = (const float*)d_in[7];
    const float* dw1 = (const float*)d_in[8];
    const float* db1 = (const float*)d_in[9];
    const float* dw2 = (const float*)d_in[10];
    const float* db2 = (const float*)d_in[11];
    const float* dw3 = (const float*)d_in[12];
    const float* db3 = (const float*)d_in[13];
    float* out = (float*)d_out;

    float* xt  = symaddr(g_xt);   float* h1  = symaddr(g_h1);
    float* h2  = symaddr(g_h2);   float* z   = symaddr(g_z);
    float* q   = symaddr(g_q);    float* d1  = symaddr(g_d1);
    float* d2  = symaddr(g_d2);   float* col = symaddr(g_col);
    float* wb1 = symaddr(g_wb1);  float* wb2 = symaddr(g_wb2);
    float* wb3 = symaddr(g_wb3);  float* en  = symaddr(g_enorm);
    __nv_bfloat16* wbd = (__nv_bfloat16*)symaddr(g_wbd);

    nchw_to_nhwc_x<<<8192, 256>>>(x, xt);
    pack_conv_w<<<(64*48+255)/256, 256>>>(w1, wb1, 64, 3, 4, 4);
    pack_conv_w<<<(128*1024+255)/256, 256>>>(w2, wb2, 128, 64, 4, 4);
    pack_conv_w<<<(64*1152+255)/256, 256>>>(w3, wb3, 64, 128, 3, 3);
    compute_enorm<<<2, 256>>>(emb, en);
    zero_loss<<<1, 1>>>();

    // L1: conv 3->64 k4 s2 p1 (M=524288, K=48, N=64): explicit col + fp32 GEMM
    im2col_conv<3,4,4,2,1,256,256,128,16,16><<<524288/16, 256>>>(xt, col);
    { DenseLoader ld; ld.A = col; ld.ldk = 48;
      sgemm_t<<<dim3(1, 4096), 256>>>(ld, wb1, 48, mk_row(h1, b1, 64, 1)); }

    // L2: conv 64->128 k4 s2 p1 (M=131072, K=1024, N=128), implicit fp32
    { ConvLoader<64,4,4,2,1,128,128,64> ld; ld.in = h1;
      sgemm_t<<<dim3(2, 1024), 256>>>(ld, wb2, 1024, mk_row(h2, b2, 128, 1)); }

    // L3: conv 128->64 k3 s1 p1 (M=131072, K=1152, N=64), implicit fp32
    { ConvLoader<128,3,3,1,1,64,64,64> ld; ld.in = h2;
      sgemm_t<<<dim3(1, 1024), 256>>>(ld, wb3, 1152, mk_row(z, b3, 64, 1)); }

    // VQ fused: distances + argmin + gather + loss (fp32)
    vq_fused<<<512, 256>>>(z, emb, en, q);

    // D1: deconv 64->128 k4 s2 p1, 4 parities (M=131072, K=256, N=128), HMMA bf16
    for (int py = 0; py < 2; ++py)
        for (int px = 0; px < 2; ++px) {
            pack_deconv_w_bf16<<<128, 256>>>(dw1, wbd, 64, 128, py, px);
            DeconvLoader<64,64,64> ld; ld.in = q; ld.py = py; ld.px = px;
            hgemm<DeconvLoader<64,64,64>, 128><<<dim3(1, 1024), 256>>>(ld, wbd, 256,
                mk_dec(d1, db1, 64*64, 64, 128, 128, py, px, (long)128*128*128, 1));
        }

    // D2: deconv 128->64 k4 s2 p1, 4 parities (M=524288, K=512, N=64), HMMA bf16
    for (int py = 0; py < 2; ++py)
        for (int px = 0; px < 2; ++px) {
            pack_deconv_w_bf16<<<128, 256>>>(dw2, wbd, 128, 64, py, px);
            DeconvLoader<128,128,128> ld; ld.in = d1; ld.py = py; ld.px = px;
            hgemm<DeconvLoader<128,128,128>, 64><<<dim3(1, 4096), 256>>>(ld, wbd, 512,
                mk_dec(d2, db2, 128*128, 128, 256, 64, py, px, (long)256*256*64, 1));
        }

    // D3: deconv 64->3 k3 s1 p1 + sigmoid -> NCHW out (fp32)
    deconv3_sigmoid<<<dim3(4, 16, 32), 256>>>(d2, dw3, db3, out);

    finalize_loss<<<1, 1>>>(out, (long)out_size - 1);
}

// round 7
// speedup vs baseline: 2.6854x; 1.2585x over previous
#include <cuda_runtime.h>
#include <cuda_bf16.h>
#include <cstdint>
#include <math.h>

// ---------------- device scratch ----------------
__device__ float  g_xt [6291456];     // x NHWC [32,256,256,3]
__device__ float  g_h1 [33554432];    // [32,128,128,64] NHWC
__device__ float  g_h2 [16777216];    // [32,64,64,128]  NHWC
__device__ float  g_z  [8388608];     // [32,64,64,64]   NHWC == flat [131072,64]
__device__ float  g_q  [8388608];
__device__ float  g_d1 [67108864];    // [32,128,128,128] NHWC
__device__ float  g_d2 [134217728];   // [32,256,256,64]  NHWC
__device__ float  g_col[25165824];    // L1 im2col only
__device__ float  g_wb1[64*48];
__device__ __nv_bfloat16 g_wb2b[131072];
__device__ __nv_bfloat16 g_wb3b[73728];
__device__ __nv_bfloat16 g_wbd[32768];
__device__ float  g_enorm[512];
__device__ double g_loss;

__device__ __forceinline__ uint32_t smem_u32(const void* p) {
    uint32_t a;
    asm("{ .reg .u64 t; cvta.to.shared.u64 t, %1; cvt.u32.u64 %0, t; }" : "=r"(a) : "l"(p));
    return a;
}
__device__ __forceinline__ uint32_t swz(uint32_t off) { return off ^ ((off >> 3) & 0x70); }

// ---------------- small kernels ----------------
__global__ void nchw_to_nhwc_x(const float* __restrict__ in, float* __restrict__ out) {
    int idx = blockIdx.x * 256 + threadIdx.x;            // 32*65536
    int n = idx >> 16, yx = idx & 65535;
    const float* ib = in + (long)n * 196608 + yx;
    float* ob = out + (long)idx * 3;
    ob[0] = ib[0]; ob[1] = ib[65536]; ob[2] = ib[131072];
}

// w[co][ci][ky][kx] -> bw[co][(ky*KW+kx)*Cin+ci]  (fp32)
__global__ void pack_conv_w(const float* __restrict__ w, float* __restrict__ bw,
                            int Cout, int Cin, int KH, int KW) {
    int idx = blockIdx.x * 256 + threadIdx.x;
    int K = Cin * KH * KW;
    if (idx >= Cout * K) return;
    int co = idx / K, rem = idx % K;
    int ci = rem / (KH * KW), r2 = rem % (KH * KW);
    bw[(long)co * K + r2 * Cin + ci] = w[idx];
}

// same but bf16 output (encoder L2/L3)
__global__ void pack_conv_w_bf16(const float* __restrict__ w, __nv_bfloat16* __restrict__ bw,
                                 int Cout, int Cin, int KH, int KW) {
    int idx = blockIdx.x * 256 + threadIdx.x;
    int K = Cin * KH * KW;
    if (idx >= Cout * K) return;
    int co = idx / K, rem = idx % K;
    int ci = rem / (KH * KW), r2 = rem % (KH * KW);
    bw[(long)co * K + r2 * Cin + ci] = __float2bfloat16(w[idx]);
}

// deconv k4s2p1 parity pack -> bf16: w[ci][co][4][4] -> bw[co][(ty*2+tx)*Cin+ci]
__global__ void pack_deconv_w_bf16(const float* __restrict__ w, __nv_bfloat16* __restrict__ bw,
                                   int Cin, int Cout, int py, int px) {
    int idx = blockIdx.x * 256 + threadIdx.x;
    if (idx >= Cout * Cin * 4) return;
    int co = idx / (Cin * 4), rem = idx % (Cin * 4);
    int ci = rem / 4, tt = rem % 4;
    int ky = (1 - py) + 2 * (tt >> 1), kx = (1 - px) + 2 * (tt & 1);
    bw[(long)co * (4 * Cin) + tt * Cin + ci] =
        __float2bfloat16(w[(((long)ci * Cout + co) * 4 + ky) * 4 + kx]);
}

__global__ void compute_enorm(const float* __restrict__ emb, float* __restrict__ en) {
    int j = blockIdx.x * 256 + threadIdx.x;
    if (j >= 512) return;
    float s = 0.f;
    const float* e = emb + (long)j * 64;
#pragma unroll 8
    for (int d = 0; d < 64; ++d) { float v = e[d]; s = fmaf(v, v, s); }
    en[j] = s;
}

__global__ void zero_loss() { g_loss = 0.0; }
__global__ void finalize_loss(float* out, long pos) {
    out[pos] = (float)(1.25 * g_loss / 8388608.0);
}

// ---------------- explicit im2col (L1 only, CIN=3) ----------------
template<int CIN, int KH, int KW, int ST, int PAD, int IH, int IW, int OW, int KT, int MB>
__global__ void __launch_bounds__(256)
im2col_conv(const float* __restrict__ in, float* __restrict__ col) {
    constexpr int K = KH * KW * CIN;
    int mi = threadIdx.x / KT, kt = threadIdx.x % KT;
    int m = blockIdx.x * MB + mi;
    int n = m / (OW * OW);
    int r = m % (OW * OW);
    int oy = r / OW, ox = r % OW;
    const float* inb = in + (long)n * IH * IW * CIN;
    float* colr = col + (long)m * K;
    for (int k = kt; k < K; k += KT) {
        int ci = k % CIN, t = k / CIN;
        int kx = t % KW, ky = t / KW;
        int iy = oy * ST - PAD + ky, ix = ox * ST - PAD + kx;
        float v = 0.f;
        if (iy >= 0 && iy < IH && ix >= 0 && ix < IW)
            v = inb[((long)iy * IW + ix) * CIN + ci];
        colr[k] = v;
    }
}

// ---------------- A-tile loaders ----------------
struct DenseLoader {
    const float* A; int ldk;
    const float* p;
    __device__ void init(int m) { p = A + (long)m * ldk; }
    __device__ void load8(int k, float4& a0, float4& a1) const {
        a0 = *(const float4*)(p + k);
        a1 = *(const float4*)(p + k + 4);
    }
};

template<int CIN, int KH, int KW, int ST, int PAD, int IH, int IW, int OW>
struct ConvLoader {
    const float* in;
    const float* base; int oy, ox;
    __device__ void init(int m) {
        int n = m / (OW * OW);
        int r = m % (OW * OW);
        oy = r / OW; ox = r % OW;
        base = in + (long)n * IH * IW * CIN;
    }
    // 32 contiguous k-values; CIN % 32 == 0 keeps them in one (ky,kx) tap
    __device__ void load32(int k, float4 (&a)[8]) const {
        int ci = k % CIN, t = k / CIN;
        int ky = t / KW, kx = t % KW;
        int iy = oy * ST - PAD + ky, ix = ox * ST - PAD + kx;
        if (iy >= 0 && iy < IH && ix >= 0 && ix < IW) {
            const float4* p = (const float4*)(base + ((long)iy * IW + ix) * CIN + ci);
#pragma unroll
            for (int i = 0; i < 8; ++i) a[i] = p[i];
        } else {
#pragma unroll
            for (int i = 0; i < 8; ++i) a[i] = make_float4(0.f,0.f,0.f,0.f);
        }
    }
};

template<int CIN, int IH, int IW>
struct DeconvLoader {
    const float* in; int py, px;
    const float* base; int u, v;
    __device__ void init(int m) {
        int n = m / (IH * IW);
        int r = m % (IH * IW);
        u = r / IW; v = r % IW;
        base = in + (long)n * IH * IW * CIN;
    }
    __device__ void load32(int k, float4 (&a)[8]) const {
        int ci = k % CIN, t = k / CIN;
        int iy = u + py - (t >> 1), ix = v + px - (t & 1);
        if (iy >= 0 && iy < IH && ix >= 0 && ix < IW) {
            const float4* p = (const float4*)(base + ((long)iy * IW + ix) * CIN + ci);
#pragma unroll
            for (int i = 0; i < 8; ++i) a[i] = p[i];
        } else {
#pragma unroll
            for (int i = 0; i < 8; ++i) a[i] = make_float4(0.f,0.f,0.f,0.f);
        }
    }
};

// ---------------- epilogue descriptor ----------------
struct Epi {
    float* out; const float* bias;
    int mode, act, ldc;          // mode 0: row-major; 1: deconv NHWC scatter
    int MPN, OV, W2, C, py, px;
    long nstride;
};

__device__ __forceinline__ long epi_base(const Epi& ep, int m) {
    if (ep.mode == 0) return (long)m * ep.ldc;
    int nn = m / ep.MPN, r = m % ep.MPN;
    int u = r / ep.OV, v = r % ep.OV;
    return (long)nn * ep.nstride +
           ((long)(2*u + ep.py) * ep.W2 + (2*v + ep.px)) * ep.C;
}

// ---------------- fp32 SGEMM (L1 only): C = A[M,K] * B[N,K]^T ----------------
template<class LD>
__global__ void __launch_bounds__(256)
sgemm_t(LD ld, const float* __restrict__ Bm, int K, Epi ep) {
    __shared__ float As[16][132];
    __shared__ float Bs[16][68];
    const int tid = threadIdx.x;
    const int m0 = blockIdx.y * 128, n0 = blockIdx.x * 64;
    const int tx = tid & 15, ty = tid >> 4;
    const int ra = tid >> 1, ca = (tid & 1) * 8;
    const int rb = tid >> 2, cb = (tid & 3) * 4;
    float acc[8][4] = {};
    ld.init(m0 + ra);
    const float* Bptr = Bm + (long)(n0 + rb) * K + cb;

    for (int k0 = 0; k0 < K; k0 += 16) {
        float4 a0, a1;
        ld.load8(k0 + ca, a0, a1);
        float4 b0 = *(const float4*)(Bptr + k0);
        As[ca+0][ra]=a0.x; As[ca+1][ra]=a0.y; As[ca+2][ra]=a0.z; As[ca+3][ra]=a0.w;
        As[ca+4][ra]=a1.x; As[ca+5][ra]=a1.y; As[ca+6][ra]=a1.z; As[ca+7][ra]=a1.w;
        Bs[cb+0][rb]=b0.x; Bs[cb+1][rb]=b0.y; Bs[cb+2][rb]=b0.z; Bs[cb+3][rb]=b0.w;
        __syncthreads();
#pragma unroll
        for (int kk = 0; kk < 16; ++kk) {
            float4 aA = *(const float4*)&As[kk][ty*8];
            float4 aB = *(const float4*)&As[kk][ty*8+4];
            float4 bb = *(const float4*)&Bs[kk][tx*4];
            float av[8] = {aA.x,aA.y,aA.z,aA.w,aB.x,aB.y,aB.z,aB.w};
            float bv[4] = {bb.x,bb.y,bb.z,bb.w};
#pragma unroll
            for (int i = 0; i < 8; ++i)
#pragma unroll
                for (int j = 0; j < 4; ++j)
                    acc[i][j] = fmaf(av[i], bv[j], acc[i][j]);
        }
        __syncthreads();
    }

    const int n_base = n0 + tx * 4;
    float bvals[4];
#pragma unroll
    for (int j = 0; j < 4; ++j) bvals[j] = ep.bias ? ep.bias[n_base + j] : 0.f;
#pragma unroll
    for (int i = 0; i < 8; ++i) {
        int m = m0 + ty * 8 + i;
        long base = (long)m * ep.ldc + n_base;
#pragma unroll
        for (int j = 0; j < 4; ++j) {
            float vv = acc[i][j] + bvals[j];
            if (ep.act) vv = fmaxf(vv, 0.f);
            ep.out[base + j] = vv;
        }
    }
}

// ---------------- HMMA bf16 GEMM, double-buffered: C = A[M,K]*B[N,K]^T ----------------
// Block 128 x TN, 8 warps 4(m) x 2(n); warp 32 x TN/2. K-chunk 64, 2-stage smem.
template<class LD, int TN>
__global__ void __launch_bounds__(256)
hgemm(LD ld, const __nv_bfloat16* __restrict__ Bw, int K, Epi ep) {
    constexpr int WN  = TN / 2;
    constexpr int NT8 = WN / 8;
    constexpr int NT16 = NT8 / 2;
    constexpr int NB = TN * 8 / 256;          // uint4 B-chunks per thread
    constexpr uint32_t ABUF = 128 * 64 * 2;   // bytes per A stage
    constexpr uint32_t BBUF = TN * 64 * 2;    // bytes per B stage
    extern __shared__ char dynsm[];
    char* sAp = dynsm;                 // 2 * ABUF
    char* sBp = dynsm + 2 * ABUF;      // 2 * BBUF

    const int tid = threadIdx.x;
    const int wid = tid >> 5, lane = tid & 31;
    const int m0 = blockIdx.y * 128;
    const int wm = (wid >> 1) * 32;
    const int wn = (wid & 1) * WN;
    const uint32_t sA0 = smem_u32(sAp), sB0 = smem_u32(sBp);

    const int row = tid >> 1, half = tid & 1;
    ld.init(m0 + row);

    float acc[2][NT8][4];
#pragma unroll
    for (int i = 0; i < 2; ++i)
#pragma unroll
        for (int j = 0; j < NT8; ++j)
#pragma unroll
            for (int c = 0; c < 4; ++c) acc[i][j][c] = 0.f;

    float4 a[8];
    uint4 breg[NB];
    ld.load32(half * 32, a);
#pragma unroll
    for (int c = 0; c < NB; ++c) {
        int i = c * 256 + tid;
        breg[c] = *(const uint4*)(Bw + (long)(i >> 3) * K + (i & 7) * 8);
    }

    int s = 0;
    for (int k0 = 0; k0 < K; k0 += 64, s ^= 1) {
        // stage fill
        char* aDst = sAp + s * ABUF;
        char* bDst = sBp + s * BBUF;
#pragma unroll
        for (int j = 0; j < 4; ++j) {
            __nv_bfloat162 p0 = __floats2bfloat162_rn(a[2*j].x,   a[2*j].y);
            __nv_bfloat162 p1 = __floats2bfloat162_rn(a[2*j].z,   a[2*j].w);
            __nv_bfloat162 p2 = __floats2bfloat162_rn(a[2*j+1].x, a[2*j+1].y);
            __nv_bfloat162 p3 = __floats2bfloat162_rn(a[2*j+1].z, a[2*j+1].w);
            uint4 u;
            u.x = *(uint32_t*)&p0; u.y = *(uint32_t*)&p1;
            u.z = *(uint32_t*)&p2; u.w = *(uint32_t*)&p3;
            uint32_t off = row * 128 + half * 64 + j * 16;
            *(uint4*)(aDst + swz(off)) = u;
        }
#pragma unroll
        for (int c = 0; c < NB; ++c) {
            int i = c * 256 + tid;
            uint32_t off = (uint32_t)(i >> 3) * 128 + (i & 7) * 16;
            *(uint4*)(bDst + swz(off)) = breg[c];
        }
        __syncthreads();

        // prefetch next chunk (overlaps MMA below)
        if (k0 + 64 < K) {
            ld.load32(k0 + 64 + half * 32, a);
#pragma unroll
            for (int c = 0; c < NB; ++c) {
                int i = c * 256 + tid;
                breg[c] = *(const uint4*)(Bw + (long)(i >> 3) * K + k0 + 64 + (i & 7) * 8);
            }
        }

        const uint32_t aBase = sA0 + s * ABUF;
        const uint32_t bBase = sB0 + s * BBUF;
#pragma unroll
        for (int ks = 0; ks < 4; ++ks) {
            uint32_t af[2][4];
#pragma unroll
            for (int mi = 0; mi < 2; ++mi) {
                uint32_t r = wm + mi * 16 + (lane & 15);
                uint32_t kb = ks * 32 + (lane >> 4) * 16;
                uint32_t ad = aBase + swz(r * 128 + kb);
                asm volatile("ldmatrix.sync.aligned.m8n8.x4.shared.b16 {%0,%1,%2,%3}, [%4];"
                    : "=r"(af[mi][0]), "=r"(af[mi][1]), "=r"(af[mi][2]), "=r"(af[mi][3])
                    : "r"(ad));
            }
            uint32_t bf[NT16][4];
#pragma unroll
            for (int ni = 0; ni < NT16; ++ni) {
                uint32_t r = wn + ni * 16 + (lane & 15);
                uint32_t kb = ks * 32 + (lane >> 4) * 16;
                uint32_t ad = bBase + swz(r * 128 + kb);
                asm volatile("ldmatrix.sync.aligned.m8n8.x4.shared.b16 {%0,%1,%2,%3}, [%4];"
                    : "=r"(bf[ni][0]), "=r"(bf[ni][1]), "=r"(bf[ni][2]), "=r"(bf[ni][3])
                    : "r"(ad));
            }
#pragma unroll
            for (int mi = 0; mi < 2; ++mi)
#pragma unroll
                for (int ni = 0; ni < NT16; ++ni) {
                    asm volatile(
                        "mma.sync.aligned.m16n8k16.row.col.f32.bf16.bf16.f32 "
                        "{%0,%1,%2,%3}, {%4,%5,%6,%7}, {%8,%9}, {%0,%1,%2,%3};"
                        : "+f"(acc[mi][2*ni][0]), "+f"(acc[mi][2*ni][1]),
                          "+f"(acc[mi][2*ni][2]), "+f"(acc[mi][2*ni][3])
                        : "r"(af[mi][0]), "r"(af[mi][1]), "r"(af[mi][2]), "r"(af[mi][3]),
                          "r"(bf[ni][0]), "r"(bf[ni][2]));
                    asm volatile(
                        "mma.sync.aligned.m16n8k16.row.col.f32.bf16.bf16.f32 "
                        "{%0,%1,%2,%3}, {%4,%5,%6,%7}, {%8,%9}, {%0,%1,%2,%3};"
                        : "+f"(acc[mi][2*ni+1][0]), "+f"(acc[mi][2*ni+1][1]),
                          "+f"(acc[mi][2*ni+1][2]), "+f"(acc[mi][2*ni+1][3])
                        : "r"(af[mi][0]), "r"(af[mi][1]), "r"(af[mi][2]), "r"(af[mi][3]),
                          "r"(bf[ni][1]), "r"(bf[ni][3]));
                }
        }
    }

    const int col = wn + (lane & 3) * 2;
#pragma unroll
    for (int mi = 0; mi < 2; ++mi) {
        int m1 = m0 + wm + mi * 16 + (lane >> 2);
        long b1 = epi_base(ep, m1);
        long b2 = epi_base(ep, m1 + 8);
#pragma unroll
        for (int j = 0; j < NT8; ++j) {
            int n = col + j * 8;
            float bi0 = ep.bias[n], bi1 = ep.bias[n + 1];
            float v0 = acc[mi][j][0] + bi0, v1 = acc[mi][j][1] + bi1;
            float v2 = acc[mi][j][2] + bi0, v3 = acc[mi][j][3] + bi1;
            if (ep.act) {
                v0 = fmaxf(v0, 0.f); v1 = fmaxf(v1, 0.f);
                v2 = fmaxf(v2, 0.f); v3 = fmaxf(v3, 0.f);
            }
            *(float2*)(ep.out + b1 + n) = make_float2(v0, v1);
            *(float2*)(ep.out + b2 + n) = make_float2(v2, v3);
        }
    }
}

// ---------------- fused VQ: distances + argmin + gather + loss ----------------
__global__ void __launch_bounds__(256)
vq_fused(const float* __restrict__ z, const float* __restrict__ emb,
         const float* __restrict__ enorm, float* __restrict__ q) {
    __shared__ float4 se[16][16];
    __shared__ float sen[16];
    __shared__ float red[256];
    const int t = threadIdx.x;
    const long m = (long)blockIdx.x * 256 + t;
    float4 zr[16];
    const float4* zp = (const float4*)(z + m * 64);
#pragma unroll
    for (int i = 0; i < 16; ++i) zr[i] = zp[i];

    float best = 3.4e38f; int bidx = 0;
    const int ljj = t >> 4, ldd = t & 15;
    for (int j0 = 0; j0 < 512; j0 += 16) {
        __syncthreads();
        se[ljj][ldd] = ((const float4*)(emb + (long)(j0 + ljj) * 64))[ldd];
        if (t < 16) sen[t] = enorm[j0 + t];
        __syncthreads();
#pragma unroll
        for (int jj = 0; jj < 16; ++jj) {
            float s0 = 0.f, s1 = 0.f, s2 = 0.f, s3 = 0.f;
#pragma unroll
            for (int d = 0; d < 16; d += 4) {
                float4 e0 = se[jj][d+0], e1 = se[jj][d+1];
                float4 e2 = se[jj][d+2], e3 = se[jj][d+3];
                s0 = fmaf(zr[d+0].x, e0.x, s0); s0 = fmaf(zr[d+0].y, e0.y, s0);
                s0 = fmaf(zr[d+0].z, e0.z, s0); s0 = fmaf(zr[d+0].w, e0.w, s0);
                s1 = fmaf(zr[d+1].x, e1.x, s1); s1 = fmaf(zr[d+1].y, e1.y, s1);
                s1 = fmaf(zr[d+1].z, e1.z, s1); s1 = fmaf(zr[d+1].w, e1.w, s1);
                s2 = fmaf(zr[d+2].x, e2.x, s2); s2 = fmaf(zr[d+2].y, e2.y, s2);
                s2 = fmaf(zr[d+2].z, e2.z, s2); s2 = fmaf(zr[d+2].w, e2.w, s2);
                s3 = fmaf(zr[d+3].x, e3.x, s3); s3 = fmaf(zr[d+3].y, e3.y, s3);
                s3 = fmaf(zr[d+3].z, e3.z, s3); s3 = fmaf(zr[d+3].w, e3.w, s3);
            }
            float dist = sen[jj] - 2.f * ((s0 + s1) + (s2 + s3));
            if (dist < best) { best = dist; bidx = j0 + jj; }
        }
    }

    const float4* ep = (const float4*)(emb + (long)bidx * 64);
    float4* qp = (float4*)(q + m * 64);
    float sq = 0.f;
#pragma unroll
    for (int i = 0; i < 16; ++i) {
        float4 e = ep[i];
        qp[i] = e;
        float d0 = e.x - zr[i].x, d1 = e.y - zr[i].y;
        float d2 = e.z - zr[i].z, d3 = e.w - zr[i].w;
        sq = fmaf(d0, d0, sq); sq = fmaf(d1, d1, sq);
        sq = fmaf(d2, d2, sq); sq = fmaf(d3, d3, sq);
    }
    red[t] = sq;
    __syncthreads();
    for (int s = 128; s; s >>= 1) {
        if (t < s) red[t] += red[t + s];
        __syncthreads();
    }
    if (t == 0) atomicAdd(&g_loss, (double)red[0]);
}

// ---------------- final deconv 64->3 k3 s1 p1 + sigmoid (direct, NCHW out) ----------------
__global__ void __launch_bounds__(256)
deconv3_sigmoid(const float* __restrict__ in, const float* __restrict__ w,
                const float* __restrict__ bias, float* __restrict__ out) {
    __shared__ float sIn[8][18][66];
    __shared__ float sW[1728];
    const int t = threadIdx.x, n = blockIdx.z;
    const int y0 = blockIdx.y * 16, x0 = blockIdx.x * 64;
    for (int i = t; i < 1728; i += 256) sW[i] = w[i];
    const int ty = t >> 4, txq = t & 15;
    float acc[3][4] = {};
    for (int cc = 0; cc < 8; ++cc) {
        __syncthreads();
        for (int idx = t; idx < 8*18*66; idx += 256) {
            int ci = idx & 7, rr = idx >> 3;
            int sx = rr % 66, sy = rr / 66;
            int gy = y0 - 1 + sy, gx = x0 - 1 + sx;
            float v = 0.f;
            if (gy >= 0 && gy < 256 && gx >= 0 && gx < 256)
                v = in[(((long)n * 256 + gy) * 256 + gx) * 64 + cc * 8 + ci];
            sIn[ci][sy][sx] = v;
        }
        __syncthreads();
#pragma unroll
        for (int c8 = 0; c8 < 8; ++c8) {
            const int ci = cc * 8 + c8;
#pragma unroll
            for (int ky = 0; ky < 3; ++ky)
#pragma unroll
            for (int kx = 0; kx < 3; ++kx) {
                const float* wp = &sW[ci*27 + ky*3 + kx];
                float w0 = wp[0], w1 = wp[9], w2 = wp[18];
                const float* ip = &sIn[c8][ty + 2 - ky][txq*4 + 2 - kx];
#pragma unroll
                for (int qq = 0; qq < 4; ++qq) {
                    float iv = ip[qq];
                    acc[0][qq] = fmaf(iv, w0, acc[0][qq]);
                    acc[1][qq] = fmaf(iv, w1, acc[1][qq]);
                    acc[2][qq] = fmaf(iv, w2, acc[2][qq]);
                }
            }
        }
    }
#pragma unroll
    for (int co = 0; co < 3; ++co) {
        float bb = bias[co];
#pragma unroll
        for (int qq = 0; qq < 4; ++qq) {
            float v = acc[co][qq] + bb;
            v = 1.f / (1.f + __expf(-v));
            out[(((long)n * 3 + co) * 256 + (y0 + ty)) * 256 + (x0 + txq*4 + qq)] = v;
        }
    }
}

// ---------------- host ----------------
static float* symaddr(const void* sym) {
    void* p = nullptr;
    cudaGetSymbolAddress(&p, sym);
    return (float*)p;
}

static Epi mk_row(float* out, const float* bias, int ldc, int act) {
    Epi e; e.out = out; e.bias = bias; e.mode = 0; e.act = act; e.ldc = ldc;
    e.MPN = e.OV = e.W2 = e.C = e.py = e.px = 0; e.nstride = 0; return e;
}
static Epi mk_dec(float* out, const float* bias, int MPN, int OV, int W2, int C,
                  int py, int px, long nstride, int act) {
    Epi e; e.out = out; e.bias = bias; e.mode = 1; e.act = act; e.ldc = 0;
    e.MPN = MPN; e.OV = OV; e.W2 = W2; e.C = C; e.py = py; e.px = px;
    e.nstride = nstride; return e;
}

typedef ConvLoader<64,4,4,2,1,128,128,64>   LdL2;
typedef ConvLoader<128,3,3,1,1,64,64,64>    LdL3;
typedef DeconvLoader<64,64,64>              LdD1;
typedef DeconvLoader<128,128,128>           LdD2;

extern "C" void kernel_launch(void* const* d_in, const int* in_sizes, int n_in,
                              void* d_out, int out_size) {
    const float* x   = (const float*)d_in[0];
    const float* w1  = (const float*)d_in[1];
    const float* b1  = (const float*)d_in[2];
    const float* w2  = (const float*)d_in[3];
    const float* b2  = (const float*)d_in[4];
    const float* w3  = (const float*)d_in[5];
    const float* b3  = (const float*)d_in[6];
    const float* emb = (const float*)d_in[7];
    const float* dw1 = (const float*)d_in[8];
    const float* db1 = (const float*)d_in[9];
    const float* dw2 = (const float*)d_in[10];
    const float* db2 = (const float*)d_in[11];
    const float* dw3 = (const float*)d_in[12];
    const float* db3 = (const float*)d_in[13];
    float* out = (float*)d_out;

    float* xt  = symaddr(g_xt);   float* h1  = symaddr(g_h1);
    float* h2  = symaddr(g_h2);   float* z   = symaddr(g_z);
    float* q   = symaddr(g_q);    float* d1  = symaddr(g_d1);
    float* d2  = symaddr(g_d2);   float* col = symaddr(g_col);
    float* wb1 = symaddr(g_wb1);  float* en  = symaddr(g_enorm);
    __nv_bfloat16* wb2b = (__nv_bfloat16*)symaddr(g_wb2b);
    __nv_bfloat16* wb3b = (__nv_bfloat16*)symaddr(g_wb3b);
    __nv_bfloat16* wbd  = (__nv_bfloat16*)symaddr(g_wbd);

    static int attr_done = 0;
    if (!attr_done) {
        cudaFuncSetAttribute((const void*)hgemm<LdL2,128>, cudaFuncAttributeMaxDynamicSharedMemorySize, 65536);
        cudaFuncSetAttribute((const void*)hgemm<LdL3,64>,  cudaFuncAttributeMaxDynamicSharedMemorySize, 65536);
        cudaFuncSetAttribute((const void*)hgemm<LdD1,128>, cudaFuncAttributeMaxDynamicSharedMemorySize, 65536);
        cudaFuncSetAttribute((const void*)hgemm<LdD2,64>,  cudaFuncAttributeMaxDynamicSharedMemorySize, 65536);
        attr_done = 1;
    }

    // L1: conv 3->64 k4 s2 p1 (M=524288, K=48, N=64): explicit col + fp32 GEMM
    nchw_to_nhwc_x<<<8192, 256>>>(x, xt);
    pack_conv_w<<<(64*48+255)/256, 256>>>(w1, wb1, 64, 3, 4, 4);
    im2col_conv<3,4,4,2,1,256,256,128,16,16><<<524288/16, 256>>>(xt, col);
    { DenseLoader ld; ld.A = col; ld.ldk = 48;
      sgemm_t<<<dim3(1, 4096), 256>>>(ld, wb1, 48, mk_row(h1, b1, 64, 1)); }

    // L2: conv 64->128 k4 s2 p1 (M=131072, K=1024, N=128), bf16 HMMA implicit
    pack_conv_w_bf16<<<(128*1024+255)/256, 256>>>(w2, wb2b, 128, 64, 4, 4);
    { LdL2 ld; ld.in = h1;
      hgemm<LdL2,128><<<dim3(1, 1024), 256, 65536>>>(ld, wb2b, 1024, mk_row(h2, b2, 128, 1)); }

    // L3: conv 128->64 k3 s1 p1 (M=131072, K=1152, N=64), bf16 HMMA implicit
    pack_conv_w_bf16<<<(64*1152+255)/256, 256>>>(w3, wb3b, 64, 128, 3, 3);
    { LdL3 ld; ld.in = h2;
      hgemm<LdL3,64><<<dim3(1, 1024), 256, 49152>>>(ld, wb3b, 1152, mk_row(z, b3, 64, 1)); }

    // VQ fused (fp32)
    compute_enorm<<<2, 256>>>(emb, en);
    zero_loss<<<1, 1>>>();
    vq_fused<<<512, 256>>>(z, emb, en, q);

    // D1: deconv 64->128 k4 s2 p1, 4 parities (M=131072, K=256, N=128)
    for (int py = 0; py < 2; ++py)
        for (int px = 0; px < 2; ++px) {
            pack_deconv_w_bf16<<<128, 256>>>(dw1, wbd, 64, 128, py, px);
            LdD1 ld; ld.in = q; ld.py = py; ld.px = px;
            hgemm<LdD1,128><<<dim3(1, 1024), 256, 65536>>>(ld, wbd, 256,
                mk_dec(d1, db1, 64*64, 64, 128, 128, py, px, (long)128*128*128, 1));
        }

    // D2: deconv 128->64 k4 s2 p1, 4 parities (M=524288, K=512, N=64)
    for (int py = 0; py < 2; ++py)
        for (int px = 0; px < 2; ++px) {
            pack_deconv_w_bf16<<<128, 256>>>(dw2, wbd, 128, 64, py, px);
            LdD2 ld; ld.in = d1; ld.py = py; ld.px = px;
            hgemm<LdD2,64><<<dim3(1, 4096), 256, 49152>>>(ld, wbd, 512,
                mk_dec(d2, db2, 128*128, 128, 256, 64, py, px, (long)256*256*64, 1));
        }

    // D3: deconv 64->3 k3 s1 p1 + sigmoid -> NCHW out (fp32)
    deconv3_sigmoid<<<dim3(4, 16, 32), 256>>>(d2, dw3, db3, out);

    finalize_loss<<<1, 1>>>(out, (long)out_size - 1);
}

// round 8
// speedup vs baseline: 3.9444x; 1.4688x over previous
#include <cuda_runtime.h>
#include <cuda_bf16.h>
#include <cstdint>
#include <math.h>

// ---------------- device scratch ----------------
__device__ float  g_xt [6291456];              // x NHWC [32,256,256,3] fp32
__device__ __nv_bfloat16 g_h1b[33554432];      // [32,128,128,64] NHWC bf16
__device__ __nv_bfloat16 g_h2b[16777216];      // [32,64,64,128]  NHWC bf16
__device__ float  g_z  [8388608];              // [32,64,64,64] fp32 (VQ/loss path)
__device__ __nv_bfloat16 g_qb [8388608];       // q bf16 (decoder input)
__device__ __nv_bfloat16 g_d1b[67108864];      // [32,128,128,128] bf16
__device__ __nv_bfloat16 g_d2b[134217728];     // [32,256,256,64]  bf16
__device__ float  g_col[25165824];             // L1 im2col (fp32)
__device__ float  g_wb1[64*48];
__device__ __nv_bfloat16 g_wb2b[131072];
__device__ __nv_bfloat16 g_wb3b[73728];
__device__ __nv_bfloat16 g_wbd[32768];
__device__ float  g_enorm[512];
__device__ double g_loss;

__device__ __forceinline__ uint32_t smem_u32(const void* p) {
    uint32_t a;
    asm("{ .reg .u64 t; cvta.to.shared.u64 t, %1; cvt.u32.u64 %0, t; }" : "=r"(a) : "l"(p));
    return a;
}
__device__ __forceinline__ uint32_t swz(uint32_t off) { return off ^ ((off >> 3) & 0x70); }

// ---------------- small kernels ----------------
__global__ void nchw_to_nhwc_x(const float* __restrict__ in, float* __restrict__ out) {
    int idx = blockIdx.x * 256 + threadIdx.x;            // 32*65536
    int n = idx >> 16, yx = idx & 65535;
    const float* ib = in + (long)n * 196608 + yx;
    float* ob = out + (long)idx * 3;
    ob[0] = ib[0]; ob[1] = ib[65536]; ob[2] = ib[131072];
}

// w[co][ci][ky][kx] -> bw[co][(ky*KW+kx)*Cin+ci]  (fp32)
__global__ void pack_conv_w(const float* __restrict__ w, float* __restrict__ bw,
                            int Cout, int Cin, int KH, int KW) {
    int idx = blockIdx.x * 256 + threadIdx.x;
    int K = Cin * KH * KW;
    if (idx >= Cout * K) return;
    int co = idx / K, rem = idx % K;
    int ci = rem / (KH * KW), r2 = rem % (KH * KW);
    bw[(long)co * K + r2 * Cin + ci] = w[idx];
}

__global__ void pack_conv_w_bf16(const float* __restrict__ w, __nv_bfloat16* __restrict__ bw,
                                 int Cout, int Cin, int KH, int KW) {
    int idx = blockIdx.x * 256 + threadIdx.x;
    int K = Cin * KH * KW;
    if (idx >= Cout * K) return;
    int co = idx / K, rem = idx % K;
    int ci = rem / (KH * KW), r2 = rem % (KH * KW);
    bw[(long)co * K + r2 * Cin + ci] = __float2bfloat16(w[idx]);
}

// deconv k4s2p1 parity pack -> bf16
__global__ void pack_deconv_w_bf16(const float* __restrict__ w, __nv_bfloat16* __restrict__ bw,
                                   int Cin, int Cout, int py, int px) {
    int idx = blockIdx.x * 256 + threadIdx.x;
    if (idx >= Cout * Cin * 4) return;
    int co = idx / (Cin * 4), rem = idx % (Cin * 4);
    int ci = rem / 4, tt = rem % 4;
    int ky = (1 - py) + 2 * (tt >> 1), kx = (1 - px) + 2 * (tt & 1);
    bw[(long)co * (4 * Cin) + tt * Cin + ci] =
        __float2bfloat16(w[(((long)ci * Cout + co) * 4 + ky) * 4 + kx]);
}

__global__ void compute_enorm(const float* __restrict__ emb, float* __restrict__ en) {
    int j = blockIdx.x * 256 + threadIdx.x;
    if (j >= 512) return;
    float s = 0.f;
    const float* e = emb + (long)j * 64;
#pragma unroll 8
    for (int d = 0; d < 64; ++d) { float v = e[d]; s = fmaf(v, v, s); }
    en[j] = s;
}

__global__ void zero_loss() { g_loss = 0.0; }
__global__ void finalize_loss(float* out, long pos) {
    out[pos] = (float)(1.25 * g_loss / 8388608.0);
}

// ---------------- explicit im2col (L1 only, CIN=3, fp32) ----------------
template<int CIN, int KH, int KW, int ST, int PAD, int IH, int IW, int OW, int KT, int MB>
__global__ void __launch_bounds__(256)
im2col_conv(const float* __restrict__ in, float* __restrict__ col) {
    constexpr int K = KH * KW * CIN;
    int mi = threadIdx.x / KT, kt = threadIdx.x % KT;
    int m = blockIdx.x * MB + mi;
    int n = m / (OW * OW);
    int r = m % (OW * OW);
    int oy = r / OW, ox = r % OW;
    const float* inb = in + (long)n * IH * IW * CIN;
    float* colr = col + (long)m * K;
    for (int k = kt; k < K; k += KT) {
        int ci = k % CIN, t = k / CIN;
        int kx = t % KW, ky = t / KW;
        int iy = oy * ST - PAD + ky, ix = ox * ST - PAD + kx;
        float v = 0.f;
        if (iy >= 0 && iy < IH && ix >= 0 && ix < IW)
            v = inb[((long)iy * IW + ix) * CIN + ci];
        colr[k] = v;
    }
}

// ---------------- A-tile loaders ----------------
struct DenseLoader {
    const float* A; int ldk;
    const float* p;
    __device__ void init(int m) { p = A + (long)m * ldk; }
    __device__ void load8(int k, float4& a0, float4& a1) const {
        a0 = *(const float4*)(p + k);
        a1 = *(const float4*)(p + k + 4);
    }
};

// bf16 implicit conv loader: 32 k-values = 64 B = 4x uint4 (CIN % 32 == 0)
template<int CIN, int KH, int KW, int ST, int PAD, int IH, int IW, int OW>
struct ConvLoaderB {
    const __nv_bfloat16* in;
    const __nv_bfloat16* base; int oy, ox;
    __device__ void init(int m) {
        int n = m / (OW * OW);
        int r = m % (OW * OW);
        oy = r / OW; ox = r % OW;
        base = in + (long)n * IH * IW * CIN;
    }
    __device__ void load32(int k, uint4 (&a)[4]) const {
        int ci = k % CIN, t = k / CIN;
        int ky = t / KW, kx = t % KW;
        int iy = oy * ST - PAD + ky, ix = ox * ST - PAD + kx;
        if (iy >= 0 && iy < IH && ix >= 0 && ix < IW) {
            const uint4* p = (const uint4*)(base + ((long)iy * IW + ix) * CIN + ci);
#pragma unroll
            for (int i = 0; i < 4; ++i) a[i] = p[i];
        } else {
#pragma unroll
            for (int i = 0; i < 4; ++i) a[i] = make_uint4(0,0,0,0);
        }
    }
};

template<int CIN, int IH, int IW>
struct DeconvLoaderB {
    const __nv_bfloat16* in; int py, px;
    const __nv_bfloat16* base; int u, v;
    __device__ void init(int m) {
        int n = m / (IH * IW);
        int r = m % (IH * IW);
        u = r / IW; v = r % IW;
        base = in + (long)n * IH * IW * CIN;
    }
    __device__ void load32(int k, uint4 (&a)[4]) const {
        int ci = k % CIN, t = k / CIN;
        int iy = u + py - (t >> 1), ix = v + px - (t & 1);
        if (iy >= 0 && iy < IH && ix >= 0 && ix < IW) {
            const uint4* p = (const uint4*)(base + ((long)iy * IW + ix) * CIN + ci);
#pragma unroll
            for (int i = 0; i < 4; ++i) a[i] = p[i];
        } else {
#pragma unroll
            for (int i = 0; i < 4; ++i) a[i] = make_uint4(0,0,0,0);
        }
    }
};

// ---------------- epilogue descriptor ----------------
struct Epi {
    float* out; const float* bias;
    int mode, act, ldc;          // mode 0: row-major; 1: deconv NHWC scatter
    int MPN, OV, W2, C, py, px;
    long nstride;
};

__device__ __forceinline__ long epi_base(const Epi& ep, int m) {
    if (ep.mode == 0) return (long)m * ep.ldc;
    int nn = m / ep.MPN, r = m % ep.MPN;
    int u = r / ep.OV, v = r % ep.OV;
    return (long)nn * ep.nstride +
           ((long)(2*u + ep.py) * ep.W2 + (2*v + ep.px)) * ep.C;
}

// ---------------- fp32 SGEMM (L1 only), bf16 output ----------------
template<class LD>
__global__ void __launch_bounds__(256)
sgemm_t(LD ld, const float* __restrict__ Bm, int K, Epi ep, __nv_bfloat16* outb) {
    __shared__ float As[16][132];
    __shared__ float Bs[16][68];
    const int tid = threadIdx.x;
    const int m0 = blockIdx.y * 128, n0 = blockIdx.x * 64;
    const int tx = tid & 15, ty = tid >> 4;
    const int ra = tid >> 1, ca = (tid & 1) * 8;
    const int rb = tid >> 2, cb = (tid & 3) * 4;
    float acc[8][4] = {};
    ld.init(m0 + ra);
    const float* Bptr = Bm + (long)(n0 + rb) * K + cb;

    for (int k0 = 0; k0 < K; k0 += 16) {
        float4 a0, a1;
        ld.load8(k0 + ca, a0, a1);
        float4 b0 = *(const float4*)(Bptr + k0);
        As[ca+0][ra]=a0.x; As[ca+1][ra]=a0.y; As[ca+2][ra]=a0.z; As[ca+3][ra]=a0.w;
        As[ca+4][ra]=a1.x; As[ca+5][ra]=a1.y; As[ca+6][ra]=a1.z; As[ca+7][ra]=a1.w;
        Bs[cb+0][rb]=b0.x; Bs[cb+1][rb]=b0.y; Bs[cb+2][rb]=b0.z; Bs[cb+3][rb]=b0.w;
        __syncthreads();
#pragma unroll
        for (int kk = 0; kk < 16; ++kk) {
            float4 aA = *(const float4*)&As[kk][ty*8];
            float4 aB = *(const float4*)&As[kk][ty*8+4];
            float4 bb = *(const float4*)&Bs[kk][tx*4];
            float av[8] = {aA.x,aA.y,aA.z,aA.w,aB.x,aB.y,aB.z,aB.w};
            float bv[4] = {bb.x,bb.y,bb.z,bb.w};
#pragma unroll
            for (int i = 0; i < 8; ++i)
#pragma unroll
                for (int j = 0; j < 4; ++j)
                    acc[i][j] = fmaf(av[i], bv[j], acc[i][j]);
        }
        __syncthreads();
    }

    const int n_base = n0 + tx * 4;
    float bvals[4];
#pragma unroll
    for (int j = 0; j < 4; ++j) bvals[j] = ep.bias ? ep.bias[n_base + j] : 0.f;
#pragma unroll
    for (int i = 0; i < 8; ++i) {
        int m = m0 + ty * 8 + i;
        long base = (long)m * ep.ldc + n_base;
        float v0 = fmaxf(acc[i][0] + bvals[0], 0.f);
        float v1 = fmaxf(acc[i][1] + bvals[1], 0.f);
        float v2 = fmaxf(acc[i][2] + bvals[2], 0.f);
        float v3 = fmaxf(acc[i][3] + bvals[3], 0.f);
        __nv_bfloat162 p0 = __floats2bfloat162_rn(v0, v1);
        __nv_bfloat162 p1 = __floats2bfloat162_rn(v2, v3);
        uint2 u; u.x = *(uint32_t*)&p0; u.y = *(uint32_t*)&p1;
        *(uint2*)(outb + base) = u;
    }
}

// ---------------- HMMA bf16 GEMM, double-buffered ----------------
// Block 128 x TN, 8 warps 4(m) x 2(n); K-chunk 64, 2-stage smem, bf16 in, fp32 or bf16 out.
template<class LD, int TN, bool OBF>
__global__ void __launch_bounds__(256)
hgemm(LD ld, const __nv_bfloat16* __restrict__ Bw, int K, Epi ep) {
    constexpr int WN  = TN / 2;
    constexpr int NT8 = WN / 8;
    constexpr int NT16 = NT8 / 2;
    constexpr int NB = TN * 8 / 256;
    constexpr uint32_t ABUF = 128 * 64 * 2;
    constexpr uint32_t BBUF = TN * 64 * 2;
    extern __shared__ char dynsm[];
    char* sAp = dynsm;
    char* sBp = dynsm + 2 * ABUF;

    const int tid = threadIdx.x;
    const int wid = tid >> 5, lane = tid & 31;
    const int m0 = blockIdx.y * 128;
    const int wm = (wid >> 1) * 32;
    const int wn = (wid & 1) * WN;
    const uint32_t sA0 = smem_u32(sAp), sB0 = smem_u32(sBp);

    const int row = tid >> 1, half = tid & 1;
    ld.init(m0 + row);

    float acc[2][NT8][4];
#pragma unroll
    for (int i = 0; i < 2; ++i)
#pragma unroll
        for (int j = 0; j < NT8; ++j)
#pragma unroll
            for (int c = 0; c < 4; ++c) acc[i][j][c] = 0.f;

    uint4 a[4];
    uint4 breg[NB];
    ld.load32(half * 32, a);
#pragma unroll
    for (int c = 0; c < NB; ++c) {
        int i = c * 256 + tid;
        breg[c] = *(const uint4*)(Bw + (long)(i >> 3) * K + (i & 7) * 8);
    }

    int s = 0;
    for (int k0 = 0; k0 < K; k0 += 64, s ^= 1) {
        char* aDst = sAp + s * ABUF;
        char* bDst = sBp + s * BBUF;
#pragma unroll
        for (int j = 0; j < 4; ++j) {
            uint32_t off = row * 128 + half * 64 + j * 16;
            *(uint4*)(aDst + swz(off)) = a[j];
        }
#pragma unroll
        for (int c = 0; c < NB; ++c) {
            int i = c * 256 + tid;
            uint32_t off = (uint32_t)(i >> 3) * 128 + (i & 7) * 16;
            *(uint4*)(bDst + swz(off)) = breg[c];
        }
        __syncthreads();

        if (k0 + 64 < K) {
            ld.load32(k0 + 64 + half * 32, a);
#pragma unroll
            for (int c = 0; c < NB; ++c) {
                int i = c * 256 + tid;
                breg[c] = *(const uint4*)(Bw + (long)(i >> 3) * K + k0 + 64 + (i & 7) * 8);
            }
        }

        const uint32_t aBase = sA0 + s * ABUF;
        const uint32_t bBase = sB0 + s * BBUF;
#pragma unroll
        for (int ks = 0; ks < 4; ++ks) {
            uint32_t af[2][4];
#pragma unroll
            for (int mi = 0; mi < 2; ++mi) {
                uint32_t r = wm + mi * 16 + (lane & 15);
                uint32_t kb = ks * 32 + (lane >> 4) * 16;
                uint32_t ad = aBase + swz(r * 128 + kb);
                asm volatile("ldmatrix.sync.aligned.m8n8.x4.shared.b16 {%0,%1,%2,%3}, [%4];"
                    : "=r"(af[mi][0]), "=r"(af[mi][1]), "=r"(af[mi][2]), "=r"(af[mi][3])
                    : "r"(ad));
            }
            uint32_t bf[NT16][4];
#pragma unroll
            for (int ni = 0; ni < NT16; ++ni) {
                uint32_t r = wn + ni * 16 + (lane & 15);
                uint32_t kb = ks * 32 + (lane >> 4) * 16;
                uint32_t ad = bBase + swz(r * 128 + kb);
                asm volatile("ldmatrix.sync.aligned.m8n8.x4.shared.b16 {%0,%1,%2,%3}, [%4];"
                    : "=r"(bf[ni][0]), "=r"(bf[ni][1]), "=r"(bf[ni][2]), "=r"(bf[ni][3])
                    : "r"(ad));
            }
#pragma unroll
            for (int mi = 0; mi < 2; ++mi)
#pragma unroll
                for (int ni = 0; ni < NT16; ++ni) {
                    asm volatile(
                        "mma.sync.aligned.m16n8k16.row.col.f32.bf16.bf16.f32 "
                        "{%0,%1,%2,%3}, {%4,%5,%6,%7}, {%8,%9}, {%0,%1,%2,%3};"
                        : "+f"(acc[mi][2*ni][0]), "+f"(acc[mi][2*ni][1]),
                          "+f"(acc[mi][2*ni][2]), "+f"(acc[mi][2*ni][3])
                        : "r"(af[mi][0]), "r"(af[mi][1]), "r"(af[mi][2]), "r"(af[mi][3]),
                          "r"(bf[ni][0]), "r"(bf[ni][2]));
                    asm volatile(
                        "mma.sync.aligned.m16n8k16.row.col.f32.bf16.bf16.f32 "
                        "{%0,%1,%2,%3}, {%4,%5,%6,%7}, {%8,%9}, {%0,%1,%2,%3};"
                        : "+f"(acc[mi][2*ni+1][0]), "+f"(acc[mi][2*ni+1][1]),
                          "+f"(acc[mi][2*ni+1][2]), "+f"(acc[mi][2*ni+1][3])
                        : "r"(af[mi][0]), "r"(af[mi][1]), "r"(af[mi][2]), "r"(af[mi][3]),
                          "r"(bf[ni][1]), "r"(bf[ni][3]));
                }
        }
    }

    const int col = wn + (lane & 3) * 2;
#pragma unroll
    for (int mi = 0; mi < 2; ++mi) {
        int m1 = m0 + wm + mi * 16 + (lane >> 2);
        long b1 = epi_base(ep, m1);
        long b2 = epi_base(ep, m1 + 8);
#pragma unroll
        for (int j = 0; j < NT8; ++j) {
            int n = col + j * 8;
            float bi0 = ep.bias[n], bi1 = ep.bias[n + 1];
            float v0 = acc[mi][j][0] + bi0, v1 = acc[mi][j][1] + bi1;
            float v2 = acc[mi][j][2] + bi0, v3 = acc[mi][j][3] + bi1;
            if (ep.act) {
                v0 = fmaxf(v0, 0.f); v1 = fmaxf(v1, 0.f);
                v2 = fmaxf(v2, 0.f); v3 = fmaxf(v3, 0.f);
            }
            if (OBF) {
                __nv_bfloat16* ob = (__nv_bfloat16*)ep.out;
                __nv_bfloat162 p0 = __floats2bfloat162_rn(v0, v1);
                __nv_bfloat162 p1 = __floats2bfloat162_rn(v2, v3);
                *(uint32_t*)(ob + b1 + n) = *(uint32_t*)&p0;
                *(uint32_t*)(ob + b2 + n) = *(uint32_t*)&p1;
            } else {
                *(float2*)(ep.out + b1 + n) = make_float2(v0, v1);
                *(float2*)(ep.out + b2 + n) = make_float2(v2, v3);
            }
        }
    }
}

// ---------------- fused VQ: distances + argmin + gather(bf16) + loss ----------------
__global__ void __launch_bounds__(256)
vq_fused(const float* __restrict__ z, const float* __restrict__ emb,
         const float* __restrict__ enorm, __nv_bfloat16* __restrict__ qb) {
    __shared__ float4 se[16][16];
    __shared__ float sen[16];
    __shared__ float red[256];
    const int t = threadIdx.x;
    const long m = (long)blockIdx.x * 256 + t;
    float4 zr[16];
    const float4* zp = (const float4*)(z + m * 64);
#pragma unroll
    for (int i = 0; i < 16; ++i) zr[i] = zp[i];

    float best = 3.4e38f; int bidx = 0;
    const int ljj = t >> 4, ldd = t & 15;
    for (int j0 = 0; j0 < 512; j0 += 16) {
        __syncthreads();
        se[ljj][ldd] = ((const float4*)(emb + (long)(j0 + ljj) * 64))[ldd];
        if (t < 16) sen[t] = enorm[j0 + t];
        __syncthreads();
#pragma unroll
        for (int jj = 0; jj < 16; ++jj) {
            float s0 = 0.f, s1 = 0.f, s2 = 0.f, s3 = 0.f;
#pragma unroll
            for (int d = 0; d < 16; d += 4) {
                float4 e0 = se[jj][d+0], e1 = se[jj][d+1];
                float4 e2 = se[jj][d+2], e3 = se[jj][d+3];
                s0 = fmaf(zr[d+0].x, e0.x, s0); s0 = fmaf(zr[d+0].y, e0.y, s0);
                s0 = fmaf(zr[d+0].z, e0.z, s0); s0 = fmaf(zr[d+0].w, e0.w, s0);
                s1 = fmaf(zr[d+1].x, e1.x, s1); s1 = fmaf(zr[d+1].y, e1.y, s1);
                s1 = fmaf(zr[d+1].z, e1.z, s1); s1 = fmaf(zr[d+1].w, e1.w, s1);
                s2 = fmaf(zr[d+2].x, e2.x, s2); s2 = fmaf(zr[d+2].y, e2.y, s2);
                s2 = fmaf(zr[d+2].z, e2.z, s2); s2 = fmaf(zr[d+2].w, e2.w, s2);
                s3 = fmaf(zr[d+3].x, e3.x, s3); s3 = fmaf(zr[d+3].y, e3.y, s3);
                s3 = fmaf(zr[d+3].z, e3.z, s3); s3 = fmaf(zr[d+3].w, e3.w, s3);
            }
            float dist = sen[jj] - 2.f * ((s0 + s1) + (s2 + s3));
            if (dist < best) { best = dist; bidx = j0 + jj; }
        }
    }

    const float4* ep = (const float4*)(emb + (long)bidx * 64);
    uint2* qp = (uint2*)(qb + m * 64);
    float sq = 0.f;
#pragma unroll
    for (int i = 0; i < 16; ++i) {
        float4 e = ep[i];
        __nv_bfloat162 p0 = __floats2bfloat162_rn(e.x, e.y);
        __nv_bfloat162 p1 = __floats2bfloat162_rn(e.z, e.w);
        uint2 u; u.x = *(uint32_t*)&p0; u.y = *(uint32_t*)&p1;
        qp[i] = u;
        float d0 = e.x - zr[i].x, d1 = e.y - zr[i].y;
        float d2 = e.z - zr[i].z, d3 = e.w - zr[i].w;
        sq = fmaf(d0, d0, sq); sq = fmaf(d1, d1, sq);
        sq = fmaf(d2, d2, sq); sq = fmaf(d3, d3, sq);
    }
    red[t] = sq;
    __syncthreads();
    for (int s = 128; s; s >>= 1) {
        if (t < s) red[t] += red[t + s];
        __syncthreads();
    }
    if (t == 0) atomicAdd(&g_loss, (double)red[0]);
}

// ---------------- final deconv 64->3 k3 s1 p1 + sigmoid (bf16 in, NCHW fp32 out) ----------------
__global__ void __launch_bounds__(256)
deconv3_sigmoid(const __nv_bfloat16* __restrict__ in, const float* __restrict__ w,
                const float* __restrict__ bias, float* __restrict__ out) {
    __shared__ float sIn[8][18][66];
    __shared__ float sW[1728];
    const int t = threadIdx.x, n = blockIdx.z;
    const int y0 = blockIdx.y * 16, x0 = blockIdx.x * 64;
    for (int i = t; i < 1728; i += 256) sW[i] = w[i];
    const int ty = t >> 4, txq = t & 15;
    float acc[3][4] = {};
    for (int cc = 0; cc < 8; ++cc) {
        __syncthreads();
        for (int idx = t; idx < 8*18*66; idx += 256) {
            int ci = idx & 7, rr = idx >> 3;
            int sx = rr % 66, sy = rr / 66;
            int gy = y0 - 1 + sy, gx = x0 - 1 + sx;
            float v = 0.f;
            if (gy >= 0 && gy < 256 && gx >= 0 && gx < 256)
                v = __bfloat162float(in[(((long)n * 256 + gy) * 256 + gx) * 64 + cc * 8 + ci]);
            sIn[ci][sy][sx] = v;
        }
        __syncthreads();
#pragma unroll
        for (int c8 = 0; c8 < 8; ++c8) {
            const int ci = cc * 8 + c8;
#pragma unroll
            for (int ky = 0; ky < 3; ++ky)
#pragma unroll
            for (int kx = 0; kx < 3; ++kx) {
                const float* wp = &sW[ci*27 + ky*3 + kx];
                float w0 = wp[0], w1 = wp[9], w2 = wp[18];
                const float* ip = &sIn[c8][ty + 2 - ky][txq*4 + 2 - kx];
#pragma unroll
                for (int qq = 0; qq < 4; ++qq) {
                    float iv = ip[qq];
                    acc[0][qq] = fmaf(iv, w0, acc[0][qq]);
                    acc[1][qq] = fmaf(iv, w1, acc[1][qq]);
                    acc[2][qq] = fmaf(iv, w2, acc[2][qq]);
                }
            }
        }
    }
#pragma unroll
    for (int co = 0; co < 3; ++co) {
        float bb = bias[co];
#pragma unroll
        for (int qq = 0; qq < 4; ++qq) {
            float v = acc[co][qq] + bb;
            v = 1.f / (1.f + __expf(-v));
            out[(((long)n * 3 + co) * 256 + (y0 + ty)) * 256 + (x0 + txq*4 + qq)] = v;
        }
    }
}

// ---------------- host ----------------
static float* symaddr(const void* sym) {
    void* p = nullptr;
    cudaGetSymbolAddress(&p, sym);
    return (float*)p;
}

static Epi mk_row(float* out, const float* bias, int ldc, int act) {
    Epi e; e.out = out; e.bias = bias; e.mode = 0; e.act = act; e.ldc = ldc;
    e.MPN = e.OV = e.W2 = e.C = e.py = e.px = 0; e.nstride = 0; return e;
}
static Epi mk_dec(float* out, const float* bias, int MPN, int OV, int W2, int C,
                  int py, int px, long nstride, int act) {
    Epi e; e.out = out; e.bias = bias; e.mode = 1; e.act = act; e.ldc = 0;
    e.MPN = MPN; e.OV = OV; e.W2 = W2; e.C = C; e.py = py; e.px = px;
    e.nstride = nstride; return e;
}

typedef ConvLoaderB<64,4,4,2,1,128,128,64>   LdL2;
typedef ConvLoaderB<128,3,3,1,1,64,64,64>    LdL3;
typedef DeconvLoaderB<64,64,64>              LdD1;
typedef DeconvLoaderB<128,128,128>           LdD2;

extern "C" void kernel_launch(void* const* d_in, const int* in_sizes, int n_in,
                              void* d_out, int out_size) {
    const float* x   = (const float*)d_in[0];
    const float* w1  = (const float*)d_in[1];
    const float* b1  = (const float*)d_in[2];
    const float* w2  = (const float*)d_in[3];
    const float* b2  = (const float*)d_in[4];
    const float* w3  = (const float*)d_in[5];
    const float* b3  = (const float*)d_in[6];
    const float* emb = (const float*)d_in[7];
    const float* dw1 = (const float*)d_in[8];
    const float* db1 = (const float*)d_in[9];
    const float* dw2 = (const float*)d_in[10];
    const float* db2 = (const float*)d_in[11];
    const float* dw3 = (const float*)d_in[12];
    const float* db3 = (const float*)d_in[13];
    float* out = (float*)d_out;

    float* xt  = symaddr(g_xt);
    float* z   = symaddr(g_z);
    float* col = symaddr(g_col);
    float* wb1 = symaddr(g_wb1);
    float* en  = symaddr(g_enorm);
    __nv_bfloat16* h1b = (__nv_bfloat16*)symaddr(g_h1b);
    __nv_bfloat16* h2b = (__nv_bfloat16*)symaddr(g_h2b);
    __nv_bfloat16* qb  = (__nv_bfloat16*)symaddr(g_qb);
    __nv_bfloat16* d1b = (__nv_bfloat16*)symaddr(g_d1b);
    __nv_bfloat16* d2b = (__nv_bfloat16*)symaddr(g_d2b);
    __nv_bfloat16* wb2b = (__nv_bfloat16*)symaddr(g_wb2b);
    __nv_bfloat16* wb3b = (__nv_bfloat16*)symaddr(g_wb3b);
    __nv_bfloat16* wbd  = (__nv_bfloat16*)symaddr(g_wbd);

    static int attr_done = 0;
    if (!attr_done) {
        cudaFuncSetAttribute((const void*)hgemm<LdL2,128,true>, cudaFuncAttributeMaxDynamicSharedMemorySize, 65536);
        cudaFuncSetAttribute((const void*)hgemm<LdL3,64,false>, cudaFuncAttributeMaxDynamicSharedMemorySize, 65536);
        cudaFuncSetAttribute((const void*)hgemm<LdD1,128,true>, cudaFuncAttributeMaxDynamicSharedMemorySize, 65536);
        cudaFuncSetAttribute((const void*)hgemm<LdD2,64,true>,  cudaFuncAttributeMaxDynamicSharedMemorySize, 65536);
        attr_done = 1;
    }

    // L1: conv 3->64 k4 s2 p1 (fp32 GEMM, bf16 output)
    nchw_to_nhwc_x<<<8192, 256>>>(x, xt);
    pack_conv_w<<<(64*48+255)/256, 256>>>(w1, wb1, 64, 3, 4, 4);
    im2col_conv<3,4,4,2,1,256,256,128,16,16><<<524288/16, 256>>>(xt, col);
    { DenseLoader ld; ld.A = col; ld.ldk = 48;
      sgemm_t<<<dim3(1, 4096), 256>>>(ld, wb1, 48, mk_row(nullptr, b1, 64, 1), h1b); }

    // L2: conv 64->128 k4 s2 p1, bf16 HMMA, bf16 out
    pack_conv_w_bf16<<<(128*1024+255)/256, 256>>>(w2, wb2b, 128, 64, 4, 4);
    { LdL2 ld; ld.in = h1b;
      hgemm<LdL2,128,true><<<dim3(1, 1024), 256, 65536>>>(ld, wb2b, 1024,
          mk_row((float*)h2b, b2, 128, 1)); }

    // L3: conv 128->64 k3 s1 p1, bf16 HMMA, fp32 z out
    pack_conv_w_bf16<<<(64*1152+255)/256, 256>>>(w3, wb3b, 64, 128, 3, 3);
    { LdL3 ld; ld.in = h2b;
      hgemm<LdL3,64,false><<<dim3(1, 1024), 256, 49152>>>(ld, wb3b, 1152,
          mk_row(z, b3, 64, 1)); }

    // VQ fused (fp32 math, bf16 q out)
    compute_enorm<<<2, 256>>>(emb, en);
    zero_loss<<<1, 1>>>();
    vq_fused<<<512, 256>>>(z, emb, en, qb);

    // D1: deconv 64->128, 4 parities, bf16 out
    for (int py = 0; py < 2; ++py)
        for (int px = 0; px < 2; ++px) {
            pack_deconv_w_bf16<<<128, 256>>>(dw1, wbd, 64, 128, py, px);
            LdD1 ld; ld.in = qb; ld.py = py; ld.px = px;
            hgemm<LdD1,128,true><<<dim3(1, 1024), 256, 65536>>>(ld, wbd, 256,
                mk_dec((float*)d1b, db1, 64*64, 64, 128, 128, py, px, (long)128*128*128, 1));
        }

    // D2: deconv 128->64, 4 parities, bf16 out
    for (int py = 0; py < 2; ++py)
        for (int px = 0; px < 2; ++px) {
            pack_deconv_w_bf16<<<128, 256>>>(dw2, wbd, 128, 64, py, px);
            LdD2 ld; ld.in = d1b; ld.py = py; ld.px = px;
            hgemm<LdD2,64,true><<<dim3(1, 4096), 256, 49152>>>(ld, wbd, 512,
                mk_dec((float*)d2b, db2, 128*128, 128, 256, 64, py, px, (long)256*256*64, 1));
        }

    // D3: deconv 64->3 k3 s1 p1 + sigmoid -> NCHW out (fp32)
    deconv3_sigmoid<<<dim3(4, 16, 32), 256>>>(d2b, dw3, db3, out);

    finalize_loss<<<1, 1>>>(out, (long)out_size - 1);
}